// round 14
// baseline (speedup 1.0000x reference)
#include <cuda_runtime.h>
#include <cuda_fp16.h>
#include <math.h>
#include <stdint.h>

// Problem constants
#define BB 2
#define SS 2048
#define DD 1024
#define HH 16
#define HD 64
#define DI 2730
#define DIP 2752           // DI padded to multiple of 64
#define MR 4096            // B*S rows
#define QKVLD (3 * DD)     // 3072
#define EPSV 1e-5f

// ---------------- scratch (device globals; no allocation allowed) ------------
// fp16 pad columns of g_ffph / g_ff2h / g_w3h (DI..DIP) stay zero: zero-init,
// never written.
__device__ float g_xn [MR * DD];
__device__ half  g_xnh[MR * DD];
__device__ half  g_qkvh[MR * QKVLD];
__device__ half  g_oh [MR * DD];
__device__ float g_h  [MR * DD];
__device__ float g_hn [MR * DD];
__device__ half  g_hnh[MR * DD];
__device__ half  g_ff2h[MR * DIP];
__device__ half  g_ffph[MR * DIP];
__device__ float g_cost[SS * 32];
__device__ float g_sint[SS * 32];
// fp16 weights
__device__ half  g_wqh[3 * DD * DD];
__device__ half  g_woh[DD * DD];
__device__ half  g_w1h[DI * DD];
__device__ half  g_w2h[DI * DD];
__device__ half  g_w3h[DD * DIP];

// ---------------- helpers ----------------------------------------------------
__device__ __forceinline__ void mma_f16(float* c, const uint32_t* a, const uint32_t* b) {
    asm volatile(
        "mma.sync.aligned.m16n8k16.row.col.f32.f16.f16.f32 "
        "{%0,%1,%2,%3},{%4,%5,%6,%7},{%8,%9},{%0,%1,%2,%3};"
        : "+f"(c[0]), "+f"(c[1]), "+f"(c[2]), "+f"(c[3])
        : "r"(a[0]), "r"(a[1]), "r"(a[2]), "r"(a[3]), "r"(b[0]), "r"(b[1]));
}

__device__ __forceinline__ void ldsm_x4(uint32_t* r, uint32_t addr) {
    asm volatile("ldmatrix.sync.aligned.m8n8.x4.shared.b16 {%0,%1,%2,%3}, [%4];"
                 : "=r"(r[0]), "=r"(r[1]), "=r"(r[2]), "=r"(r[3]) : "r"(addr));
}
__device__ __forceinline__ void ldsm_x2(uint32_t* r, uint32_t addr) {
    asm volatile("ldmatrix.sync.aligned.m8n8.x2.shared.b16 {%0,%1}, [%2];"
                 : "=r"(r[0]), "=r"(r[1]) : "r"(addr));
}

__device__ __forceinline__ void cp_async16(uint32_t dst, const void* src, int szbytes) {
    asm volatile("cp.async.ca.shared.global [%0], [%1], 16, %2;"
                 :: "r"(dst), "l"(src), "r"(szbytes));
}
__device__ __forceinline__ void cp_commit() {
    asm volatile("cp.async.commit_group;");
}
template <int N>
__device__ __forceinline__ void cp_wait() {
    asm volatile("cp.async.wait_group %0;" :: "n"(N));
}

// raw ex2 (single MUFU, no scaling FMA)
__device__ __forceinline__ float ex2(float x) {
    float y;
    asm("ex2.approx.f32 %0, %1;" : "=f"(y) : "f"(x));
    return y;
}

// ---------------- rmsnorm: fp32 + fp16 outputs -------------------------------
__global__ void rmsnorm_kernel(const float* __restrict__ X,
                               const float* __restrict__ gamma,
                               float* __restrict__ Y,
                               half* __restrict__ Yh)
{
    const int row = blockIdx.x;
    const float4* xr = (const float4*)(X + (size_t)row * DD);
    const float4* gm = (const float4*)gamma;
    float4*       yr = (float4*)(Y + (size_t)row * DD);

    const int t = threadIdx.x;
    float4 v = xr[t];
    float s = v.x * v.x + v.y * v.y + v.z * v.z + v.w * v.w;
    #pragma unroll
    for (int o = 16; o > 0; o >>= 1) s += __shfl_xor_sync(0xffffffffu, s, o);

    __shared__ float red[8];
    __shared__ float rinv_sh;
    if ((t & 31) == 0) red[t >> 5] = s;
    __syncthreads();
    if (t == 0) {
        float tt = 0.f;
        #pragma unroll
        for (int i = 0; i < 8; i++) tt += red[i];
        rinv_sh = rsqrtf(tt * (1.0f / DD) + EPSV);
    }
    __syncthreads();
    const float rinv = rinv_sh;
    float4 g = gm[t];
    float4 r = make_float4(v.x * rinv * g.x, v.y * rinv * g.y,
                           v.z * rinv * g.z, v.w * rinv * g.w);
    yr[t] = r;
    half* yh = Yh + (size_t)row * DD + t * 4;
    *(half2*)(yh)     = __floats2half2_rn(r.x, r.y);
    *(half2*)(yh + 2) = __floats2half2_rn(r.z, r.w);
}

// ---------------- fused prep: all weight cvts + w3 pad + rope tables ---------
#define PQ  (3 * DD * DD / 4)
#define PO  (DD * DD / 4)
#define P1  (DI * DD / 4)
#define P2  (DI * DD / 4)
#define P3  (DD * DIP / 4)
#define PT  (SS * 32 / 4)
#define PREP_TOTAL (PQ + PO + P1 + P2 + P3 + PT)

__global__ void prep_kernel(const float* __restrict__ w_qkv, const float* __restrict__ w_out,
                            const float* __restrict__ w1, const float* __restrict__ w2,
                            const float* __restrict__ w3,
                            half* __restrict__ wqh, half* __restrict__ woh,
                            half* __restrict__ w1h, half* __restrict__ w2h,
                            half* __restrict__ w3h,
                            float* __restrict__ cost, float* __restrict__ sint)
{
    int idx = blockIdx.x * 256 + threadIdx.x;
    if (idx >= PREP_TOTAL) return;

    if (idx < PQ + PO + P1 + P2) {
        const float* S; half* H; int i = idx;
        if (i < PQ)                { S = w_qkv; H = wqh; }
        else if ((i -= PQ) < PO)   { S = w_out; H = woh; }
        else if ((i -= PO) < P1)   { S = w1;    H = w1h; }
        else                       { i -= P1; S = w2; H = w2h; }
        float4 v = ((const float4*)S)[i];
        *(half2*)(H + (size_t)i * 4)     = __floats2half2_rn(v.x, v.y);
        *(half2*)(H + (size_t)i * 4 + 2) = __floats2half2_rn(v.z, v.w);
    } else if (idx < PQ + PO + P1 + P2 + P3) {
        int i = idx - (PQ + PO + P1 + P2);
        int base = i * 4;
        int row = base / DIP, col = base % DIP;
        #pragma unroll
        for (int e = 0; e < 4; e++) {
            int c = col + e;
            float x = (c < DI) ? w3[(size_t)row * DI + c] : 0.f;
            w3h[(size_t)row * DIP + c] = __float2half_rn(x);
        }
    } else {
        int i = (idx - (PQ + PO + P1 + P2 + P3)) * 4;
        #pragma unroll
        for (int e = 0; e < 4; e++) {
            int id = i + e;
            int ii = id & 31, s = id >> 5;
            float theta = powf(10000.f, -(float)ii / 32.f);
            float sn, cs;
            sincosf((float)s * theta, &sn, &cs);
            cost[id] = cs;
            sint[id] = sn;
        }
    }
}

// ---------------- fp16 tensor-core GEMM: C = A[M,K] * B[N,K]^T (+ epilogue)
// CTA 128x128x64(halves), 256 threads (8 warps 2x4, warp tile 64x32),
// cp.async 3-stage, ldmatrix fragment loads. Operands fp16, accum fp32.
// MODE 1: C  = z + bias + res                (fp32)
// MODE 2: Ch = half(silu(z + bias))          (fp16 out)
// MODE 3: Ch = half((z + bias) * resh)       (fp16 out, fp16 res)
// MODE 4: Ch = half(rope(z + bias))          (fp16 qkv out)
#define GBM 128
#define GBN 128
#define GBK 64                          // halves per K-tile
#define GLDSH 72                        // smem row stride in halves (+8 pad)
#define NSTG 3
#define ASTG (GBM * GLDSH)
#define BSTG (GBN * GLDSH)
#define GEMM_SMEM_BYTES (NSTG * (ASTG + BSTG) * 2)    // 110592

template <int MODE>
__global__ __launch_bounds__(256, 2)
void gemm_tc_kernel(const half* __restrict__ A,
                    const half* __restrict__ Bm,
                    const float* __restrict__ bias,
                    const float* __restrict__ res,
                    const half* __restrict__ resh,
                    float* __restrict__ C,
                    half* __restrict__ Ch,
                    const float* __restrict__ cost,
                    const float* __restrict__ sint,
                    int M, int N, int K, int ldc)
{
    extern __shared__ half hsmem[];
    half* Asm = hsmem;                      // [NSTG][GBM][GLDSH]
    half* Bsm = hsmem + NSTG * ASTG;        // [NSTG][GBN][GLDSH]

    const int tid = threadIdx.x;
    const int m0 = blockIdx.y * GBM;
    const int n0 = blockIdx.x * GBN;

    const int loadRow   = tid >> 3;
    const int loadChunk = (tid & 7) * 8;

    const uint32_t aSmBase = (uint32_t)__cvta_generic_to_shared(Asm) +
                             (uint32_t)((loadRow * GLDSH + loadChunk) * 2);
    const uint32_t bSmBase = (uint32_t)__cvta_generic_to_shared(Bsm) +
                             (uint32_t)((loadRow * GLDSH + loadChunk) * 2);

    const int wid  = tid >> 5;
    const int lane = tid & 31;
    const int wm = (wid >> 2) * 64;
    const int wn = (wid & 3) * 32;
    const int tg = lane >> 2;
    const int tq = lane & 3;

    const int aLaneOff = (wm + (lane & 15)) * GLDSH + (lane >> 4) * 8;
    const int bLaneOff = (wn + (lane & 7)) * GLDSH + ((lane >> 3) & 1) * 8;
    const uint32_t aSmLd = (uint32_t)__cvta_generic_to_shared(Asm) + (uint32_t)(aLaneOff * 2);
    const uint32_t bSmLd = (uint32_t)__cvta_generic_to_shared(Bsm) + (uint32_t)(bLaneOff * 2);

    float acc[4][4][4];
    #pragma unroll
    for (int i = 0; i < 4; i++)
        #pragma unroll
        for (int j = 0; j < 4; j++)
            #pragma unroll
            for (int e = 0; e < 4; e++) acc[i][j][e] = 0.f;

    const int KT = K / GBK;

    auto load_stage = [&](int s, int kt) {
        const int k0 = kt * GBK;
        const uint32_t aDst = aSmBase + (uint32_t)(s * ASTG * 2);
        const uint32_t bDst = bSmBase + (uint32_t)(s * BSTG * 2);
        #pragma unroll
        for (int i = 0; i < 4; i++) {
            int r = loadRow + 32 * i;
            const half* srcA = A + (size_t)(m0 + r) * K + (k0 + loadChunk);
            cp_async16(aDst + (uint32_t)(i * 32 * GLDSH * 2), srcA, 16);
            int gn = n0 + r;
            int ok = (gn < N);
            const half* srcB = Bm + (size_t)(ok ? gn : 0) * K + (k0 + loadChunk);
            cp_async16(bDst + (uint32_t)(i * 32 * GLDSH * 2), srcB, ok ? 16 : 0);
        }
        cp_commit();
    };

    load_stage(0, 0);
    if (KT > 1) load_stage(1, 1);

    for (int kt = 0; kt < KT; kt++) {
        const int s = kt % NSTG;
        if (kt + 1 < KT) cp_wait<1>(); else cp_wait<0>();
        __syncthreads();

        const uint32_t aLd = aSmLd + (uint32_t)(s * ASTG * 2);
        const uint32_t bLd = bSmLd + (uint32_t)(s * BSTG * 2);

        #pragma unroll
        for (int kk = 0; kk < GBK; kk += 16) {
            uint32_t af[4][4], bf[4][2];
            #pragma unroll
            for (int ti = 0; ti < 4; ti++)
                ldsm_x4(af[ti], aLd + (uint32_t)((16 * ti * GLDSH + kk) * 2));
            #pragma unroll
            for (int tj = 0; tj < 4; tj++)
                ldsm_x2(bf[tj], bLd + (uint32_t)((8 * tj * GLDSH + kk) * 2));
            #pragma unroll
            for (int ti = 0; ti < 4; ti++)
                #pragma unroll
                for (int tj = 0; tj < 4; tj++)
                    mma_f16(acc[ti][tj], af[ti], bf[tj]);
        }

        if (kt + 2 < KT) load_stage((kt + 2) % NSTG, kt + 2);
    }

    // ------------- epilogue ---------------------------------------------------
    #pragma unroll
    for (int ti = 0; ti < 4; ti++) {
        const int r0 = m0 + wm + 16 * ti + tg;
        const int r1 = r0 + 8;
        #pragma unroll
        for (int tj = 0; tj < 4; tj++) {
            const int cc = n0 + wn + 8 * tj + 2 * tq;
            const float* c = acc[ti][tj];
            if (MODE == 4) {
                float z0 = c[0] + bias[cc];
                float z1 = c[1] + bias[cc + 1];
                float z2 = c[2] + bias[cc];
                float z3 = c[3] + bias[cc + 1];
                size_t row0 = (size_t)r0 * ldc;
                size_t row1 = (size_t)r1 * ldc;
                if (cc >= 2 * DD) {
                    *(half2*)&Ch[row0 + cc] = __floats2half2_rn(z0, z1);
                    *(half2*)&Ch[row1 + cc] = __floats2half2_rn(z2, z3);
                } else {
                    int i = (cc & 63) >> 1;
                    int basec = cc & ~63;
                    int s0 = r0 & (SS - 1);
                    int s1 = r1 & (SS - 1);
                    float cs0 = cost[s0 * 32 + i], sn0 = sint[s0 * 32 + i];
                    float cs1 = cost[s1 * 32 + i], sn1 = sint[s1 * 32 + i];
                    Ch[row0 + basec + i]      = __float2half_rn(z0 * cs0 - z1 * sn0);
                    Ch[row0 + basec + 32 + i] = __float2half_rn(z0 * sn0 + z1 * cs0);
                    Ch[row1 + basec + i]      = __float2half_rn(z2 * cs1 - z3 * sn1);
                    Ch[row1 + basec + 32 + i] = __float2half_rn(z2 * sn1 + z3 * cs1);
                }
            } else if (MODE == 3) {
                if (cc < N) {
                    size_t o0 = (size_t)r0 * ldc + cc;
                    size_t o1 = (size_t)r1 * ldc + cc;
                    float2 b2v = *(const float2*)&bias[cc];
                    float2 rv0 = __half22float2(*(const half2*)(resh + o0));
                    float2 rv1 = __half22float2(*(const half2*)(resh + o1));
                    *(half2*)(Ch + o0) = __floats2half2_rn((c[0] + b2v.x) * rv0.x,
                                                           (c[1] + b2v.y) * rv0.y);
                    *(half2*)(Ch + o1) = __floats2half2_rn((c[2] + b2v.x) * rv1.x,
                                                           (c[3] + b2v.y) * rv1.y);
                }
            } else if (MODE == 2) {
                if (cc < N) {
                    size_t o0 = (size_t)r0 * ldc + cc;
                    size_t o1 = (size_t)r1 * ldc + cc;
                    float2 b2v = *(const float2*)&bias[cc];
                    float z0 = c[0] + b2v.x, z1 = c[1] + b2v.y;
                    float z2 = c[2] + b2v.x, z3 = c[3] + b2v.y;
                    *(half2*)(Ch + o0) = __floats2half2_rn(z0 / (1.f + __expf(-z0)),
                                                           z1 / (1.f + __expf(-z1)));
                    *(half2*)(Ch + o1) = __floats2half2_rn(z2 / (1.f + __expf(-z2)),
                                                           z3 / (1.f + __expf(-z3)));
                }
            } else {
                #pragma unroll
                for (int e = 0; e < 2; e++) {
                    const int col = cc + e;
                    if (col < N) {
                        size_t o0 = (size_t)r0 * ldc + col;
                        size_t o1 = (size_t)r1 * ldc + col;
                        float z0 = c[e]     + bias[col];
                        float z1 = c[e + 2] + bias[col];
                        C[o0] = z0 + res[o0];
                        C[o1] = z1 + res[o1];
                    }
                }
            }
        }
    }
}

// ---------------- tensor-core fused causal attention -------------------------
// Reads Q/K/V strided from the fp16 qkv buffer; writes fp16 O.
// Softmax runs in log2 domain (Q pre-scaled by log2(e)/8, ex2.approx).
#define AQT 128
#define AKT 64
#define KHSTR 72
#define VSTR 72
#define ATTN_K_BYTES (2 * AKT * KHSTR * 2)
#define ATTN_V_BYTES (2 * HD * VSTR * 2)
#define ATTN_SMEM_BYTES (ATTN_K_BYTES + ATTN_V_BYTES)

__global__ __launch_bounds__(256, 2)
void attn_tc_kernel(const half* __restrict__ QKV,
                    half* __restrict__ O)
{
    extern __shared__ char smraw[];
    half* Ksm = (half*)smraw;
    half* Vsm = (half*)(smraw + ATTN_K_BYTES);

    const int bh = blockIdx.y;
    const int bidx = bh >> 4, hidx = bh & 15;
    const int qt = gridDim.x - 1 - blockIdx.x;   // heaviest tiles first
    const int m0 = qt * AQT;

    const half* Qb = QKV + (size_t)(bidx * SS) * QKVLD + hidx * HD;
    const half* Kb = Qb + DD;
    const half* Vb = Qb + 2 * DD;

    const int tid  = threadIdx.x;
    const int wid  = tid >> 5;
    const int lane = tid & 31;
    const int tg   = lane >> 2;
    const int tq   = lane & 3;

    const int r0 = m0 + wid * 16 + tg;
    const int r1 = r0 + 8;

    // Q fragments scaled by log2(e)/8 (log2-domain softmax)
    uint32_t qf[4][4];
    {
        const half2 scale = __half2half2(__float2half(0.18033688f));
        const half* q0 = Qb + (size_t)r0 * QKVLD;
        const half* q1 = q0 + 8 * QKVLD;
        #pragma unroll
        for (int kc = 0; kc < 4; kc++) {
            half2 h0 = __hmul2(*(const half2*)(q0 + kc * 16 + 2 * tq), scale);
            half2 h1 = __hmul2(*(const half2*)(q1 + kc * 16 + 2 * tq), scale);
            half2 h2 = __hmul2(*(const half2*)(q0 + kc * 16 + 2 * tq + 8), scale);
            half2 h3 = __hmul2(*(const half2*)(q1 + kc * 16 + 2 * tq + 8), scale);
            qf[kc][0] = *(uint32_t*)&h0;
            qf[kc][1] = *(uint32_t*)&h1;
            qf[kc][2] = *(uint32_t*)&h2;
            qf[kc][3] = *(uint32_t*)&h3;
        }
    }

    float oacc[8][4];
    #pragma unroll
    for (int dt = 0; dt < 8; dt++)
        #pragma unroll
        for (int e = 0; e < 4; e++) oacc[dt][e] = 0.f;
    float mrow0 = -1e30f, mrow1 = -1e30f, lrow0 = 0.f, lrow1 = 0.f;

    auto load_stage = [&](int st, int kt) {
        const int n0 = kt * AKT;
        {
            half* kdst = Ksm + st * AKT * KHSTR;
            int j  = tid >> 2;
            int d0 = (tid & 3) * 16;
            const half* krow = Kb + (size_t)(n0 + j) * QKVLD + d0;
            *(uint4*)(kdst + j * KHSTR + d0)     = *(const uint4*)(krow);
            *(uint4*)(kdst + j * KHSTR + d0 + 8) = *(const uint4*)(krow + 8);
        }
        {
            half* vdst = Vsm + st * HD * VSTR;
            const int d0  = tid & 31;
            const int jp0 = tid >> 5;
            #pragma unroll
            for (int ii = 0; ii < 4; ii++) {
                int jp = jp0 + 8 * ii;
                #pragma unroll
                for (int dd = 0; dd < 2; dd++) {
                    int d = d0 + 32 * dd;
                    half a = Vb[(size_t)(n0 + 2 * jp)     * QKVLD + d];
                    half b = Vb[(size_t)(n0 + 2 * jp + 1) * QKVLD + d];
                    *(half2*)(vdst + d * VSTR + 2 * jp) = __halves2half2(a, b);
                }
            }
        }
    };

    load_stage(0, 0);

    const int ktend = 2 * qt + 1;
    for (int kt = 0; kt <= ktend; kt++) {
        const int s = kt & 1;
        const int n0 = kt * AKT;
        __syncthreads();
        if (kt < ktend) load_stage(s ^ 1, kt + 1);

        const half* ks = Ksm + s * AKT * KHSTR;
        const half* vs = Vsm + s * HD * VSTR;

        float sc[8][4];
        #pragma unroll
        for (int nt = 0; nt < 8; nt++) {
            #pragma unroll
            for (int e = 0; e < 4; e++) sc[nt][e] = 0.f;
            const half* krow = ks + (nt * 8 + tg) * KHSTR;
            #pragma unroll
            for (int kc = 0; kc < 4; kc++) {
                uint32_t bf[2];
                bf[0] = *(const uint32_t*)(krow + kc * 16 + 2 * tq);
                bf[1] = *(const uint32_t*)(krow + kc * 16 + 2 * tq + 8);
                mma_f16(sc[nt], qf[kc], bf);
            }
        }

        if (kt >= 2 * qt) {
            #pragma unroll
            for (int nt = 0; nt < 8; nt++) {
                int jg = n0 + nt * 8 + 2 * tq;
                if (jg     > r0) sc[nt][0] = -1e30f;
                if (jg + 1 > r0) sc[nt][1] = -1e30f;
                if (jg     > r1) sc[nt][2] = -1e30f;
                if (jg + 1 > r1) sc[nt][3] = -1e30f;
            }
        }

        float tm0 = -1e30f, tm1 = -1e30f;
        #pragma unroll
        for (int nt = 0; nt < 8; nt++) {
            tm0 = fmaxf(tm0, fmaxf(sc[nt][0], sc[nt][1]));
            tm1 = fmaxf(tm1, fmaxf(sc[nt][2], sc[nt][3]));
        }
        tm0 = fmaxf(tm0, __shfl_xor_sync(0xffffffffu, tm0, 1));
        tm0 = fmaxf(tm0, __shfl_xor_sync(0xffffffffu, tm0, 2));
        tm1 = fmaxf(tm1, __shfl_xor_sync(0xffffffffu, tm1, 1));
        tm1 = fmaxf(tm1, __shfl_xor_sync(0xffffffffu, tm1, 2));

        float mn0 = fmaxf(mrow0, tm0), mn1 = fmaxf(mrow1, tm1);
        float al0 = ex2(mrow0 - mn0), al1 = ex2(mrow1 - mn1);
        mrow0 = mn0; mrow1 = mn1;

        float sum0 = 0.f, sum1 = 0.f;
        #pragma unroll
        for (int nt = 0; nt < 8; nt++) {
            sc[nt][0] = ex2(sc[nt][0] - mn0); sum0 += sc[nt][0];
            sc[nt][1] = ex2(sc[nt][1] - mn0); sum0 += sc[nt][1];
            sc[nt][2] = ex2(sc[nt][2] - mn1); sum1 += sc[nt][2];
            sc[nt][3] = ex2(sc[nt][3] - mn1); sum1 += sc[nt][3];
        }
        sum0 += __shfl_xor_sync(0xffffffffu, sum0, 1);
        sum0 += __shfl_xor_sync(0xffffffffu, sum0, 2);
        sum1 += __shfl_xor_sync(0xffffffffu, sum1, 1);
        sum1 += __shfl_xor_sync(0xffffffffu, sum1, 2);
        lrow0 = lrow0 * al0 + sum0;
        lrow1 = lrow1 * al1 + sum1;

        #pragma unroll
        for (int dt = 0; dt < 8; dt++) {
            oacc[dt][0] *= al0; oacc[dt][1] *= al0;
            oacc[dt][2] *= al1; oacc[dt][3] *= al1;
        }

        #pragma unroll
        for (int kc = 0; kc < 4; kc++) {
            uint32_t pa[4];
            half2 p0 = __floats2half2_rn(sc[2 * kc][0],     sc[2 * kc][1]);
            half2 p1 = __floats2half2_rn(sc[2 * kc][2],     sc[2 * kc][3]);
            half2 p2 = __floats2half2_rn(sc[2 * kc + 1][0], sc[2 * kc + 1][1]);
            half2 p3 = __floats2half2_rn(sc[2 * kc + 1][2], sc[2 * kc + 1][3]);
            pa[0] = *(uint32_t*)&p0; pa[1] = *(uint32_t*)&p1;
            pa[2] = *(uint32_t*)&p2; pa[3] = *(uint32_t*)&p3;
            #pragma unroll
            for (int dt = 0; dt < 8; dt++) {
                const half* vrow = vs + (dt * 8 + tg) * VSTR;
                uint32_t vb[2];
                vb[0] = *(const uint32_t*)(vrow + kc * 16 + 2 * tq);
                vb[1] = *(const uint32_t*)(vrow + kc * 16 + 2 * tq + 8);
                mma_f16(oacc[dt], pa, vb);
            }
        }
    }

    // ---- write O (fp16) in [B,S,D] ---------------------------------------------
    const float inv0 = 1.f / lrow0;
    const float inv1 = 1.f / lrow1;
    #pragma unroll
    for (int dt = 0; dt < 8; dt++) {
        int dcol = hidx * HD + dt * 8 + 2 * tq;
        *(half2*)&O[((size_t)(bidx * SS + r0)) * DD + dcol] =
            __floats2half2_rn(oacc[dt][0] * inv0, oacc[dt][1] * inv0);
        *(half2*)&O[((size_t)(bidx * SS + r1)) * DD + dcol] =
            __floats2half2_rn(oacc[dt][2] * inv1, oacc[dt][3] * inv1);
    }
}

// ---------------- launch -----------------------------------------------------
extern "C" void kernel_launch(void* const* d_in, const int* in_sizes, int n_in,
                              void* d_out, int out_size)
{
    const float* x          = (const float*)d_in[0];
    // d_in[1] = mask (unused — causal handled analytically)
    const float* gamma_attn = (const float*)d_in[2];
    const float* w_qkv      = (const float*)d_in[3];
    const float* b_qkv      = (const float*)d_in[4];
    const float* w_out      = (const float*)d_in[5];
    const float* b_out      = (const float*)d_in[6];
    const float* gamma_ffn  = (const float*)d_in[7];
    const float* w1         = (const float*)d_in[8];
    const float* b1         = (const float*)d_in[9];
    const float* w2         = (const float*)d_in[10];
    const float* b2         = (const float*)d_in[11];
    const float* w3         = (const float*)d_in[12];
    const float* b3         = (const float*)d_in[13];
    float* out = (float*)d_out;

    float *xn, *h, *hn, *cost, *sint;
    half *xnh, *qkvh, *oh, *hnh, *ff2h, *ffph, *wqh, *woh, *w1h, *w2h, *w3h;
    cudaGetSymbolAddress((void**)&xn,   g_xn);
    cudaGetSymbolAddress((void**)&xnh,  g_xnh);
    cudaGetSymbolAddress((void**)&qkvh, g_qkvh);
    cudaGetSymbolAddress((void**)&oh,   g_oh);
    cudaGetSymbolAddress((void**)&h,    g_h);
    cudaGetSymbolAddress((void**)&hn,   g_hn);
    cudaGetSymbolAddress((void**)&hnh,  g_hnh);
    cudaGetSymbolAddress((void**)&ff2h, g_ff2h);
    cudaGetSymbolAddress((void**)&ffph, g_ffph);
    cudaGetSymbolAddress((void**)&cost, g_cost);
    cudaGetSymbolAddress((void**)&sint, g_sint);
    cudaGetSymbolAddress((void**)&wqh,  g_wqh);
    cudaGetSymbolAddress((void**)&woh,  g_woh);
    cudaGetSymbolAddress((void**)&w1h,  g_w1h);
    cudaGetSymbolAddress((void**)&w2h,  g_w2h);
    cudaGetSymbolAddress((void**)&w3h,  g_w3h);

    cudaFuncSetAttribute(attn_tc_kernel, cudaFuncAttributeMaxDynamicSharedMemorySize,
                         ATTN_SMEM_BYTES);
    cudaFuncSetAttribute(gemm_tc_kernel<1>, cudaFuncAttributeMaxDynamicSharedMemorySize,
                         GEMM_SMEM_BYTES);
    cudaFuncSetAttribute(gemm_tc_kernel<2>, cudaFuncAttributeMaxDynamicSharedMemorySize,
                         GEMM_SMEM_BYTES);
    cudaFuncSetAttribute(gemm_tc_kernel<3>, cudaFuncAttributeMaxDynamicSharedMemorySize,
                         GEMM_SMEM_BYTES);
    cudaFuncSetAttribute(gemm_tc_kernel<4>, cudaFuncAttributeMaxDynamicSharedMemorySize,
                         GEMM_SMEM_BYTES);

    // 0. fused prep: weight fp16 conversions + w3 pad + rope tables
    prep_kernel<<<(PREP_TOTAL + 255) / 256, 256>>>(
        w_qkv, w_out, w1, w2, w3, wqh, woh, w1h, w2h, w3h, cost, sint);

    // 1. xn = rmsnorm(x, gamma_attn)  (fp32 + fp16)
    rmsnorm_kernel<<<MR, 256>>>(x, gamma_attn, xn, xnh);

    // 2. qkvh = half(rope(xn @ w_qkv^T + b_qkv))   [4096 x 3072], K=1024
    gemm_tc_kernel<4><<<dim3(QKVLD / GBN, MR / GBM), 256, GEMM_SMEM_BYTES>>>(
        xnh, wqh, b_qkv, nullptr, nullptr, nullptr, qkvh, cost, sint,
        MR, QKVLD, DD, QKVLD);

    // 3. fused causal attention (fp16 qkv) -> oh fp16 in [B,S,D]
    attn_tc_kernel<<<dim3(SS / AQT, BB * HH), 256, ATTN_SMEM_BYTES>>>(qkvh, oh);

    // 4. h = xn + o @ w_out^T + b_out              [4096 x 1024], K=1024
    gemm_tc_kernel<1><<<dim3(DD / GBN, MR / GBM), 256, GEMM_SMEM_BYTES>>>(
        oh, woh, b_out, xn, nullptr, h, nullptr, nullptr, nullptr,
        MR, DD, DD, DD);

    // 5. hn = rmsnorm(h, gamma_ffn)  (fp32 + fp16)
    rmsnorm_kernel<<<MR, 256>>>(h, gamma_ffn, hn, hnh);

    // 6a. ff2h = half(silu(hn @ w2^T + b2))        [4096 x 2730] @ ldc DIP
    gemm_tc_kernel<2><<<dim3((DI + GBN - 1) / GBN, MR / GBM), 256, GEMM_SMEM_BYTES>>>(
        hnh, w2h, b2, nullptr, nullptr, nullptr, ff2h, nullptr, nullptr,
        MR, DI, DD, DIP);

    // 6b. ffph = half((hn @ w1^T + b1) * ff2h)     [4096 x 2730] @ ldc DIP
    gemm_tc_kernel<3><<<dim3((DI + GBN - 1) / GBN, MR / GBM), 256, GEMM_SMEM_BYTES>>>(
        hnh, w1h, b1, nullptr, ff2h, nullptr, ffph, nullptr, nullptr,
        MR, DI, DD, DIP);

    // 7. out = hn + ffp @ w3^T + b3                [4096 x 1024], K=2752
    gemm_tc_kernel<1><<<dim3(DD / GBN, MR / GBM), 256, GEMM_SMEM_BYTES>>>(
        ffph, w3h, b3, hn, nullptr, out, nullptr, nullptr, nullptr,
        MR, DD, DIP, DD);
}

// round 15
// speedup vs baseline: 1.0350x; 1.0350x over previous
#include <cuda_runtime.h>
#include <cuda_fp16.h>
#include <math.h>
#include <stdint.h>

// Problem constants
#define BB 2
#define SS 2048
#define DD 1024
#define HH 16
#define HD 64
#define DI 2730
#define DIP 2752           // DI padded to multiple of 64
#define MR 4096            // B*S rows
#define QKVLD (3 * DD)     // 3072
#define EPSV 1e-5f

// ---------------- scratch (device globals; no allocation allowed) ------------
// fp16 pad columns of g_ffph / g_ff2h / g_w3h (DI..DIP) stay zero: zero-init,
// never written.
__device__ float g_xn [MR * DD];
__device__ half  g_xnh[MR * DD];
__device__ half  g_qkvh[MR * QKVLD];
__device__ half  g_oh [MR * DD];
__device__ float g_h  [MR * DD];
__device__ float g_hn [MR * DD];
__device__ half  g_hnh[MR * DD];
__device__ half  g_ff2h[MR * DIP];
__device__ half  g_ffph[MR * DIP];
__device__ float g_cost[SS * 32];
__device__ float g_sint[SS * 32];
// fp16 weights
__device__ half  g_wqh[3 * DD * DD];
__device__ half  g_woh[DD * DD];
__device__ half  g_w1h[DI * DD];
__device__ half  g_w2h[DI * DD];
__device__ half  g_w3h[DD * DIP];

// ---------------- helpers ----------------------------------------------------
__device__ __forceinline__ void mma_f16(float* c, const uint32_t* a, const uint32_t* b) {
    asm volatile(
        "mma.sync.aligned.m16n8k16.row.col.f32.f16.f16.f32 "
        "{%0,%1,%2,%3},{%4,%5,%6,%7},{%8,%9},{%0,%1,%2,%3};"
        : "+f"(c[0]), "+f"(c[1]), "+f"(c[2]), "+f"(c[3])
        : "r"(a[0]), "r"(a[1]), "r"(a[2]), "r"(a[3]), "r"(b[0]), "r"(b[1]));
}

__device__ __forceinline__ void ldsm_x4(uint32_t* r, uint32_t addr) {
    asm volatile("ldmatrix.sync.aligned.m8n8.x4.shared.b16 {%0,%1,%2,%3}, [%4];"
                 : "=r"(r[0]), "=r"(r[1]), "=r"(r[2]), "=r"(r[3]) : "r"(addr));
}
__device__ __forceinline__ void ldsm_x2(uint32_t* r, uint32_t addr) {
    asm volatile("ldmatrix.sync.aligned.m8n8.x2.shared.b16 {%0,%1}, [%2];"
                 : "=r"(r[0]), "=r"(r[1]) : "r"(addr));
}

__device__ __forceinline__ void cp_async16(uint32_t dst, const void* src, int szbytes) {
    asm volatile("cp.async.ca.shared.global [%0], [%1], 16, %2;"
                 :: "r"(dst), "l"(src), "r"(szbytes));
}
__device__ __forceinline__ void cp_commit() {
    asm volatile("cp.async.commit_group;");
}
template <int N>
__device__ __forceinline__ void cp_wait() {
    asm volatile("cp.async.wait_group %0;" :: "n"(N));
}

// raw ex2 (single MUFU, no scaling FMA)
__device__ __forceinline__ float ex2(float x) {
    float y;
    asm("ex2.approx.f32 %0, %1;" : "=f"(y) : "f"(x));
    return y;
}

// ---------------- rmsnorm: fp32 + fp16 outputs -------------------------------
__global__ void rmsnorm_kernel(const float* __restrict__ X,
                               const float* __restrict__ gamma,
                               float* __restrict__ Y,
                               half* __restrict__ Yh)
{
    const int row = blockIdx.x;
    const float4* xr = (const float4*)(X + (size_t)row * DD);
    const float4* gm = (const float4*)gamma;
    float4*       yr = (float4*)(Y + (size_t)row * DD);

    const int t = threadIdx.x;
    float4 v = xr[t];
    float s = v.x * v.x + v.y * v.y + v.z * v.z + v.w * v.w;
    #pragma unroll
    for (int o = 16; o > 0; o >>= 1) s += __shfl_xor_sync(0xffffffffu, s, o);

    __shared__ float red[8];
    __shared__ float rinv_sh;
    if ((t & 31) == 0) red[t >> 5] = s;
    __syncthreads();
    if (t == 0) {
        float tt = 0.f;
        #pragma unroll
        for (int i = 0; i < 8; i++) tt += red[i];
        rinv_sh = rsqrtf(tt * (1.0f / DD) + EPSV);
    }
    __syncthreads();
    const float rinv = rinv_sh;
    float4 g = gm[t];
    float4 r = make_float4(v.x * rinv * g.x, v.y * rinv * g.y,
                           v.z * rinv * g.z, v.w * rinv * g.w);
    yr[t] = r;
    half* yh = Yh + (size_t)row * DD + t * 4;
    *(half2*)(yh)     = __floats2half2_rn(r.x, r.y);
    *(half2*)(yh + 2) = __floats2half2_rn(r.z, r.w);
}

// ---------------- fused prep: all weight cvts + w3 pad + rope tables ---------
#define PQ  (3 * DD * DD / 4)
#define PO  (DD * DD / 4)
#define P1  (DI * DD / 4)
#define P2  (DI * DD / 4)
#define P3  (DD * DIP / 4)
#define PT  (SS * 32 / 4)
#define PREP_TOTAL (PQ + PO + P1 + P2 + P3 + PT)

__global__ void prep_kernel(const float* __restrict__ w_qkv, const float* __restrict__ w_out,
                            const float* __restrict__ w1, const float* __restrict__ w2,
                            const float* __restrict__ w3,
                            half* __restrict__ wqh, half* __restrict__ woh,
                            half* __restrict__ w1h, half* __restrict__ w2h,
                            half* __restrict__ w3h,
                            float* __restrict__ cost, float* __restrict__ sint)
{
    int idx = blockIdx.x * 256 + threadIdx.x;
    if (idx >= PREP_TOTAL) return;

    if (idx < PQ + PO + P1 + P2) {
        const float* S; half* H; int i = idx;
        if (i < PQ)                { S = w_qkv; H = wqh; }
        else if ((i -= PQ) < PO)   { S = w_out; H = woh; }
        else if ((i -= PO) < P1)   { S = w1;    H = w1h; }
        else                       { i -= P1; S = w2; H = w2h; }
        float4 v = ((const float4*)S)[i];
        *(half2*)(H + (size_t)i * 4)     = __floats2half2_rn(v.x, v.y);
        *(half2*)(H + (size_t)i * 4 + 2) = __floats2half2_rn(v.z, v.w);
    } else if (idx < PQ + PO + P1 + P2 + P3) {
        int i = idx - (PQ + PO + P1 + P2);
        int base = i * 4;
        int row = base / DIP, col = base % DIP;
        #pragma unroll
        for (int e = 0; e < 4; e++) {
            int c = col + e;
            float x = (c < DI) ? w3[(size_t)row * DI + c] : 0.f;
            w3h[(size_t)row * DIP + c] = __float2half_rn(x);
        }
    } else {
        int i = (idx - (PQ + PO + P1 + P2 + P3)) * 4;
        #pragma unroll
        for (int e = 0; e < 4; e++) {
            int id = i + e;
            int ii = id & 31, s = id >> 5;
            float theta = powf(10000.f, -(float)ii / 32.f);
            float sn, cs;
            sincosf((float)s * theta, &sn, &cs);
            cost[id] = cs;
            sint[id] = sn;
        }
    }
}

// ---------------- fp16 tensor-core GEMM: C = A[M,K] * B[N,K]^T (+ epilogue)
// CTA 128x128x64(halves), 256 threads (8 warps 2x4, warp tile 64x32),
// cp.async 2-stage, ldmatrix fragment loads. Operands fp16, accum fp32.
// MODE 1: C  = z + bias + res                (fp32)
// MODE 2: Ch = half(silu(z + bias))          (fp16 out)
// MODE 3: Ch = half((z + bias) * resh)       (fp16 out, fp16 res)
// MODE 4: Ch = half(rope(z + bias))          (fp16 qkv out)
#define GBM 128
#define GBN 128
#define GBK 64                          // halves per K-tile
#define GLDSH 72                        // smem row stride in halves (+8 pad)
#define ASTG (GBM * GLDSH)              // halves per A stage
#define BSTG (GBN * GLDSH)
#define GEMM_SMEM_BYTES (2 * (ASTG + BSTG) * 2)    // 73728

template <int MODE>
__global__ __launch_bounds__(256, 2)
void gemm_tc_kernel(const half* __restrict__ A,
                    const half* __restrict__ Bm,
                    const float* __restrict__ bias,
                    const float* __restrict__ res,
                    const half* __restrict__ resh,
                    float* __restrict__ C,
                    half* __restrict__ Ch,
                    const float* __restrict__ cost,
                    const float* __restrict__ sint,
                    int M, int N, int K, int ldc)
{
    extern __shared__ half hsmem[];
    half* Asm = hsmem;                      // [2][GBM][GLDSH]
    half* Bsm = hsmem + 2 * ASTG;           // [2][GBN][GLDSH]

    const int tid = threadIdx.x;
    const int m0 = blockIdx.y * GBM;
    const int n0 = blockIdx.x * GBN;

    const int loadRow   = tid >> 3;         // 0..31
    const int loadChunk = (tid & 7) * 8;    // halves: 0,8,...,56

    const uint32_t aSmBase = (uint32_t)__cvta_generic_to_shared(Asm) +
                             (uint32_t)((loadRow * GLDSH + loadChunk) * 2);
    const uint32_t bSmBase = (uint32_t)__cvta_generic_to_shared(Bsm) +
                             (uint32_t)((loadRow * GLDSH + loadChunk) * 2);

    const int wid  = tid >> 5;
    const int lane = tid & 31;
    const int wm = (wid >> 2) * 64;         // 0 / 64
    const int wn = (wid & 3) * 32;          // 0 / 32 / 64 / 96
    const int tg = lane >> 2;               // 0..7
    const int tq = lane & 3;                // 0..3

    // ldmatrix lane addressing (halves)
    const int aLaneOff = (wm + (lane & 15)) * GLDSH + (lane >> 4) * 8;
    const int bLaneOff = (wn + (lane & 7)) * GLDSH + ((lane >> 3) & 1) * 8;
    const uint32_t aSmLd = (uint32_t)__cvta_generic_to_shared(Asm) + (uint32_t)(aLaneOff * 2);
    const uint32_t bSmLd = (uint32_t)__cvta_generic_to_shared(Bsm) + (uint32_t)(bLaneOff * 2);

    float acc[4][4][4];
    #pragma unroll
    for (int i = 0; i < 4; i++)
        #pragma unroll
        for (int j = 0; j < 4; j++)
            #pragma unroll
            for (int e = 0; e < 4; e++) acc[i][j][e] = 0.f;

    const int KT = K / GBK;

    auto load_stage = [&](int s, int kt) {
        const int k0 = kt * GBK;
        const uint32_t aDst = aSmBase + (uint32_t)(s * ASTG * 2);
        const uint32_t bDst = bSmBase + (uint32_t)(s * BSTG * 2);
        #pragma unroll
        for (int i = 0; i < 4; i++) {
            int r = loadRow + 32 * i;
            const half* srcA = A + (size_t)(m0 + r) * K + (k0 + loadChunk);
            cp_async16(aDst + (uint32_t)(i * 32 * GLDSH * 2), srcA, 16);
            int gn = n0 + r;
            int ok = (gn < N);
            const half* srcB = Bm + (size_t)(ok ? gn : 0) * K + (k0 + loadChunk);
            cp_async16(bDst + (uint32_t)(i * 32 * GLDSH * 2), srcB, ok ? 16 : 0);
        }
    };

    load_stage(0, 0);
    cp_commit();

    for (int kt = 0; kt < KT; kt++) {
        const int s = kt & 1;
        if (kt + 1 < KT) {
            load_stage(s ^ 1, kt + 1);
            cp_commit();
            cp_wait<1>();
        } else {
            cp_wait<0>();
        }
        __syncthreads();

        const uint32_t aLd = aSmLd + (uint32_t)(s * ASTG * 2);
        const uint32_t bLd = bSmLd + (uint32_t)(s * BSTG * 2);

        #pragma unroll
        for (int kk = 0; kk < GBK; kk += 16) {
            uint32_t af[4][4], bf[4][2];
            #pragma unroll
            for (int ti = 0; ti < 4; ti++)
                ldsm_x4(af[ti], aLd + (uint32_t)((16 * ti * GLDSH + kk) * 2));
            #pragma unroll
            for (int tj = 0; tj < 4; tj++)
                ldsm_x2(bf[tj], bLd + (uint32_t)((8 * tj * GLDSH + kk) * 2));
            #pragma unroll
            for (int ti = 0; ti < 4; ti++)
                #pragma unroll
                for (int tj = 0; tj < 4; tj++)
                    mma_f16(acc[ti][tj], af[ti], bf[tj]);
        }
        __syncthreads();
    }

    // ------------- epilogue ---------------------------------------------------
    #pragma unroll
    for (int ti = 0; ti < 4; ti++) {
        const int r0 = m0 + wm + 16 * ti + tg;
        const int r1 = r0 + 8;
        #pragma unroll
        for (int tj = 0; tj < 4; tj++) {
            const int cc = n0 + wn + 8 * tj + 2 * tq;
            const float* c = acc[ti][tj];
            if (MODE == 4) {
                float z0 = c[0] + bias[cc];
                float z1 = c[1] + bias[cc + 1];
                float z2 = c[2] + bias[cc];
                float z3 = c[3] + bias[cc + 1];
                size_t row0 = (size_t)r0 * ldc;
                size_t row1 = (size_t)r1 * ldc;
                if (cc >= 2 * DD) {
                    *(half2*)&Ch[row0 + cc] = __floats2half2_rn(z0, z1);
                    *(half2*)&Ch[row1 + cc] = __floats2half2_rn(z2, z3);
                } else {
                    int i = (cc & 63) >> 1;
                    int basec = cc & ~63;
                    int s0 = r0 & (SS - 1);
                    int s1 = r1 & (SS - 1);
                    float cs0 = cost[s0 * 32 + i], sn0 = sint[s0 * 32 + i];
                    float cs1 = cost[s1 * 32 + i], sn1 = sint[s1 * 32 + i];
                    Ch[row0 + basec + i]      = __float2half_rn(z0 * cs0 - z1 * sn0);
                    Ch[row0 + basec + 32 + i] = __float2half_rn(z0 * sn0 + z1 * cs0);
                    Ch[row1 + basec + i]      = __float2half_rn(z2 * cs1 - z3 * sn1);
                    Ch[row1 + basec + 32 + i] = __float2half_rn(z2 * sn1 + z3 * cs1);
                }
            } else if (MODE == 3) {
                if (cc < N) {
                    size_t o0 = (size_t)r0 * ldc + cc;
                    size_t o1 = (size_t)r1 * ldc + cc;
                    float2 b2v = *(const float2*)&bias[cc];
                    float2 rv0 = __half22float2(*(const half2*)(resh + o0));
                    float2 rv1 = __half22float2(*(const half2*)(resh + o1));
                    *(half2*)(Ch + o0) = __floats2half2_rn((c[0] + b2v.x) * rv0.x,
                                                           (c[1] + b2v.y) * rv0.y);
                    *(half2*)(Ch + o1) = __floats2half2_rn((c[2] + b2v.x) * rv1.x,
                                                           (c[3] + b2v.y) * rv1.y);
                }
            } else if (MODE == 2) {
                if (cc < N) {
                    size_t o0 = (size_t)r0 * ldc + cc;
                    size_t o1 = (size_t)r1 * ldc + cc;
                    float2 b2v = *(const float2*)&bias[cc];
                    float z0 = c[0] + b2v.x, z1 = c[1] + b2v.y;
                    float z2 = c[2] + b2v.x, z3 = c[3] + b2v.y;
                    *(half2*)(Ch + o0) = __floats2half2_rn(z0 / (1.f + __expf(-z0)),
                                                           z1 / (1.f + __expf(-z1)));
                    *(half2*)(Ch + o1) = __floats2half2_rn(z2 / (1.f + __expf(-z2)),
                                                           z3 / (1.f + __expf(-z3)));
                }
            } else {
                #pragma unroll
                for (int e = 0; e < 2; e++) {
                    const int col = cc + e;
                    if (col < N) {
                        size_t o0 = (size_t)r0 * ldc + col;
                        size_t o1 = (size_t)r1 * ldc + col;
                        float z0 = c[e]     + bias[col];
                        float z1 = c[e + 2] + bias[col];
                        C[o0] = z0 + res[o0];
                        C[o1] = z1 + res[o1];
                    }
                }
            }
        }
    }
}

// ---------------- tensor-core fused causal attention -------------------------
// Reads Q/K/V strided from the fp16 qkv buffer; writes fp16 O.
// Softmax in log2 domain (Q pre-scaled by log2(e)/8, ex2.approx);
// heaviest causal tiles launched first.
#define AQT 128
#define AKT 64
#define KHSTR 72
#define VSTR 72
#define ATTN_K_BYTES (2 * AKT * KHSTR * 2)
#define ATTN_V_BYTES (2 * HD * VSTR * 2)
#define ATTN_SMEM_BYTES (ATTN_K_BYTES + ATTN_V_BYTES)

__global__ __launch_bounds__(256, 2)
void attn_tc_kernel(const half* __restrict__ QKV,
                    half* __restrict__ O)
{
    extern __shared__ char smraw[];
    half* Ksm = (half*)smraw;
    half* Vsm = (half*)(smraw + ATTN_K_BYTES);

    const int bh = blockIdx.y;
    const int bidx = bh >> 4, hidx = bh & 15;
    const int qt = gridDim.x - 1 - blockIdx.x;   // heaviest tiles first
    const int m0 = qt * AQT;

    const half* Qb = QKV + (size_t)(bidx * SS) * QKVLD + hidx * HD;
    const half* Kb = Qb + DD;
    const half* Vb = Qb + 2 * DD;

    const int tid  = threadIdx.x;
    const int wid  = tid >> 5;
    const int lane = tid & 31;
    const int tg   = lane >> 2;
    const int tq   = lane & 3;

    const int r0 = m0 + wid * 16 + tg;
    const int r1 = r0 + 8;

    // Q fragments scaled by log2(e)/8 (log2-domain softmax)
    uint32_t qf[4][4];
    {
        const half2 scale = __half2half2(__float2half(0.18033688f));
        const half* q0 = Qb + (size_t)r0 * QKVLD;
        const half* q1 = q0 + 8 * QKVLD;
        #pragma unroll
        for (int kc = 0; kc < 4; kc++) {
            half2 h0 = __hmul2(*(const half2*)(q0 + kc * 16 + 2 * tq), scale);
            half2 h1 = __hmul2(*(const half2*)(q1 + kc * 16 + 2 * tq), scale);
            half2 h2 = __hmul2(*(const half2*)(q0 + kc * 16 + 2 * tq + 8), scale);
            half2 h3 = __hmul2(*(const half2*)(q1 + kc * 16 + 2 * tq + 8), scale);
            qf[kc][0] = *(uint32_t*)&h0;
            qf[kc][1] = *(uint32_t*)&h1;
            qf[kc][2] = *(uint32_t*)&h2;
            qf[kc][3] = *(uint32_t*)&h3;
        }
    }

    float oacc[8][4];
    #pragma unroll
    for (int dt = 0; dt < 8; dt++)
        #pragma unroll
        for (int e = 0; e < 4; e++) oacc[dt][e] = 0.f;
    float mrow0 = -1e30f, mrow1 = -1e30f, lrow0 = 0.f, lrow1 = 0.f;

    auto load_stage = [&](int st, int kt) {
        const int n0 = kt * AKT;
        {
            half* kdst = Ksm + st * AKT * KHSTR;
            int j  = tid >> 2;
            int d0 = (tid & 3) * 16;
            const half* krow = Kb + (size_t)(n0 + j) * QKVLD + d0;
            *(uint4*)(kdst + j * KHSTR + d0)     = *(const uint4*)(krow);
            *(uint4*)(kdst + j * KHSTR + d0 + 8) = *(const uint4*)(krow + 8);
        }
        {
            half* vdst = Vsm + st * HD * VSTR;
            const int d0  = tid & 31;
            const int jp0 = tid >> 5;
            #pragma unroll
            for (int ii = 0; ii < 4; ii++) {
                int jp = jp0 + 8 * ii;
                #pragma unroll
                for (int dd = 0; dd < 2; dd++) {
                    int d = d0 + 32 * dd;
                    half a = Vb[(size_t)(n0 + 2 * jp)     * QKVLD + d];
                    half b = Vb[(size_t)(n0 + 2 * jp + 1) * QKVLD + d];
                    *(half2*)(vdst + d * VSTR + 2 * jp) = __halves2half2(a, b);
                }
            }
        }
    };

    load_stage(0, 0);

    const int ktend = 2 * qt + 1;
    for (int kt = 0; kt <= ktend; kt++) {
        const int s = kt & 1;
        const int n0 = kt * AKT;
        __syncthreads();
        if (kt < ktend) load_stage(s ^ 1, kt + 1);

        const half* ks = Ksm + s * AKT * KHSTR;
        const half* vs = Vsm + s * HD * VSTR;

        float sc[8][4];
        #pragma unroll
        for (int nt = 0; nt < 8; nt++) {
            #pragma unroll
            for (int e = 0; e < 4; e++) sc[nt][e] = 0.f;
            const half* krow = ks + (nt * 8 + tg) * KHSTR;
            #pragma unroll
            for (int kc = 0; kc < 4; kc++) {
                uint32_t bf[2];
                bf[0] = *(const uint32_t*)(krow + kc * 16 + 2 * tq);
                bf[1] = *(const uint32_t*)(krow + kc * 16 + 2 * tq + 8);
                mma_f16(sc[nt], qf[kc], bf);
            }
        }

        if (kt >= 2 * qt) {
            #pragma unroll
            for (int nt = 0; nt < 8; nt++) {
                int jg = n0 + nt * 8 + 2 * tq;
                if (jg     > r0) sc[nt][0] = -1e30f;
                if (jg + 1 > r0) sc[nt][1] = -1e30f;
                if (jg     > r1) sc[nt][2] = -1e30f;
                if (jg + 1 > r1) sc[nt][3] = -1e30f;
            }
        }

        float tm0 = -1e30f, tm1 = -1e30f;
        #pragma unroll
        for (int nt = 0; nt < 8; nt++) {
            tm0 = fmaxf(tm0, fmaxf(sc[nt][0], sc[nt][1]));
            tm1 = fmaxf(tm1, fmaxf(sc[nt][2], sc[nt][3]));
        }
        tm0 = fmaxf(tm0, __shfl_xor_sync(0xffffffffu, tm0, 1));
        tm0 = fmaxf(tm0, __shfl_xor_sync(0xffffffffu, tm0, 2));
        tm1 = fmaxf(tm1, __shfl_xor_sync(0xffffffffu, tm1, 1));
        tm1 = fmaxf(tm1, __shfl_xor_sync(0xffffffffu, tm1, 2));

        float mn0 = fmaxf(mrow0, tm0), mn1 = fmaxf(mrow1, tm1);
        float al0 = ex2(mrow0 - mn0), al1 = ex2(mrow1 - mn1);
        mrow0 = mn0; mrow1 = mn1;

        float sum0 = 0.f, sum1 = 0.f;
        #pragma unroll
        for (int nt = 0; nt < 8; nt++) {
            sc[nt][0] = ex2(sc[nt][0] - mn0); sum0 += sc[nt][0];
            sc[nt][1] = ex2(sc[nt][1] - mn0); sum0 += sc[nt][1];
            sc[nt][2] = ex2(sc[nt][2] - mn1); sum1 += sc[nt][2];
            sc[nt][3] = ex2(sc[nt][3] - mn1); sum1 += sc[nt][3];
        }
        sum0 += __shfl_xor_sync(0xffffffffu, sum0, 1);
        sum0 += __shfl_xor_sync(0xffffffffu, sum0, 2);
        sum1 += __shfl_xor_sync(0xffffffffu, sum1, 1);
        sum1 += __shfl_xor_sync(0xffffffffu, sum1, 2);
        lrow0 = lrow0 * al0 + sum0;
        lrow1 = lrow1 * al1 + sum1;

        #pragma unroll
        for (int dt = 0; dt < 8; dt++) {
            oacc[dt][0] *= al0; oacc[dt][1] *= al0;
            oacc[dt][2] *= al1; oacc[dt][3] *= al1;
        }

        #pragma unroll
        for (int kc = 0; kc < 4; kc++) {
            uint32_t pa[4];
            half2 p0 = __floats2half2_rn(sc[2 * kc][0],     sc[2 * kc][1]);
            half2 p1 = __floats2half2_rn(sc[2 * kc][2],     sc[2 * kc][3]);
            half2 p2 = __floats2half2_rn(sc[2 * kc + 1][0], sc[2 * kc + 1][1]);
            half2 p3 = __floats2half2_rn(sc[2 * kc + 1][2], sc[2 * kc + 1][3]);
            pa[0] = *(uint32_t*)&p0; pa[1] = *(uint32_t*)&p1;
            pa[2] = *(uint32_t*)&p2; pa[3] = *(uint32_t*)&p3;
            #pragma unroll
            for (int dt = 0; dt < 8; dt++) {
                const half* vrow = vs + (dt * 8 + tg) * VSTR;
                uint32_t vb[2];
                vb[0] = *(const uint32_t*)(vrow + kc * 16 + 2 * tq);
                vb[1] = *(const uint32_t*)(vrow + kc * 16 + 2 * tq + 8);
                mma_f16(oacc[dt], pa, vb);
            }
        }
    }

    // ---- write O (fp16) in [B,S,D] ---------------------------------------------
    const float inv0 = 1.f / lrow0;
    const float inv1 = 1.f / lrow1;
    #pragma unroll
    for (int dt = 0; dt < 8; dt++) {
        int dcol = hidx * HD + dt * 8 + 2 * tq;
        *(half2*)&O[((size_t)(bidx * SS + r0)) * DD + dcol] =
            __floats2half2_rn(oacc[dt][0] * inv0, oacc[dt][1] * inv0);
        *(half2*)&O[((size_t)(bidx * SS + r1)) * DD + dcol] =
            __floats2half2_rn(oacc[dt][2] * inv1, oacc[dt][3] * inv1);
    }
}

// ---------------- launch -----------------------------------------------------
extern "C" void kernel_launch(void* const* d_in, const int* in_sizes, int n_in,
                              void* d_out, int out_size)
{
    const float* x          = (const float*)d_in[0];
    // d_in[1] = mask (unused — causal handled analytically)
    const float* gamma_attn = (const float*)d_in[2];
    const float* w_qkv      = (const float*)d_in[3];
    const float* b_qkv      = (const float*)d_in[4];
    const float* w_out      = (const float*)d_in[5];
    const float* b_out      = (const float*)d_in[6];
    const float* gamma_ffn  = (const float*)d_in[7];
    const float* w1         = (const float*)d_in[8];
    const float* b1         = (const float*)d_in[9];
    const float* w2         = (const float*)d_in[10];
    const float* b2         = (const float*)d_in[11];
    const float* w3         = (const float*)d_in[12];
    const float* b3         = (const float*)d_in[13];
    float* out = (float*)d_out;

    float *xn, *h, *hn, *cost, *sint;
    half *xnh, *qkvh, *oh, *hnh, *ff2h, *ffph, *wqh, *woh, *w1h, *w2h, *w3h;
    cudaGetSymbolAddress((void**)&xn,   g_xn);
    cudaGetSymbolAddress((void**)&xnh,  g_xnh);
    cudaGetSymbolAddress((void**)&qkvh, g_qkvh);
    cudaGetSymbolAddress((void**)&oh,   g_oh);
    cudaGetSymbolAddress((void**)&h,    g_h);
    cudaGetSymbolAddress((void**)&hn,   g_hn);
    cudaGetSymbolAddress((void**)&hnh,  g_hnh);
    cudaGetSymbolAddress((void**)&ff2h, g_ff2h);
    cudaGetSymbolAddress((void**)&ffph, g_ffph);
    cudaGetSymbolAddress((void**)&cost, g_cost);
    cudaGetSymbolAddress((void**)&sint, g_sint);
    cudaGetSymbolAddress((void**)&wqh,  g_wqh);
    cudaGetSymbolAddress((void**)&woh,  g_woh);
    cudaGetSymbolAddress((void**)&w1h,  g_w1h);
    cudaGetSymbolAddress((void**)&w2h,  g_w2h);
    cudaGetSymbolAddress((void**)&w3h,  g_w3h);

    cudaFuncSetAttribute(attn_tc_kernel, cudaFuncAttributeMaxDynamicSharedMemorySize,
                         ATTN_SMEM_BYTES);
    cudaFuncSetAttribute(gemm_tc_kernel<1>, cudaFuncAttributeMaxDynamicSharedMemorySize,
                         GEMM_SMEM_BYTES);
    cudaFuncSetAttribute(gemm_tc_kernel<2>, cudaFuncAttributeMaxDynamicSharedMemorySize,
                         GEMM_SMEM_BYTES);
    cudaFuncSetAttribute(gemm_tc_kernel<3>, cudaFuncAttributeMaxDynamicSharedMemorySize,
                         GEMM_SMEM_BYTES);
    cudaFuncSetAttribute(gemm_tc_kernel<4>, cudaFuncAttributeMaxDynamicSharedMemorySize,
                         GEMM_SMEM_BYTES);

    // 0. fused prep: weight fp16 conversions + w3 pad + rope tables
    prep_kernel<<<(PREP_TOTAL + 255) / 256, 256>>>(
        w_qkv, w_out, w1, w2, w3, wqh, woh, w1h, w2h, w3h, cost, sint);

    // 1. xn = rmsnorm(x, gamma_attn)  (fp32 + fp16)
    rmsnorm_kernel<<<MR, 256>>>(x, gamma_attn, xn, xnh);

    // 2. qkvh = half(rope(xn @ w_qkv^T + b_qkv))   [4096 x 3072], K=1024
    gemm_tc_kernel<4><<<dim3(QKVLD / GBN, MR / GBM), 256, GEMM_SMEM_BYTES>>>(
        xnh, wqh, b_qkv, nullptr, nullptr, nullptr, qkvh, cost, sint,
        MR, QKVLD, DD, QKVLD);

    // 3. fused causal attention (fp16 qkv) -> oh fp16 in [B,S,D]
    attn_tc_kernel<<<dim3(SS / AQT, BB * HH), 256, ATTN_SMEM_BYTES>>>(qkvh, oh);

    // 4. h = xn + o @ w_out^T + b_out              [4096 x 1024], K=1024
    gemm_tc_kernel<1><<<dim3(DD / GBN, MR / GBM), 256, GEMM_SMEM_BYTES>>>(
        oh, woh, b_out, xn, nullptr, h, nullptr, nullptr, nullptr,
        MR, DD, DD, DD);

    // 5. hn = rmsnorm(h, gamma_ffn)  (fp32 + fp16)
    rmsnorm_kernel<<<MR, 256>>>(h, gamma_ffn, hn, hnh);

    // 6a. ff2h = half(silu(hn @ w2^T + b2))        [4096 x 2730] @ ldc DIP
    gemm_tc_kernel<2><<<dim3((DI + GBN - 1) / GBN, MR / GBM), 256, GEMM_SMEM_BYTES>>>(
        hnh, w2h, b2, nullptr, nullptr, nullptr, ff2h, nullptr, nullptr,
        MR, DI, DD, DIP);

    // 6b. ffph = half((hn @ w1^T + b1) * ff2h)     [4096 x 2730] @ ldc DIP
    gemm_tc_kernel<3><<<dim3((DI + GBN - 1) / GBN, MR / GBM), 256, GEMM_SMEM_BYTES>>>(
        hnh, w1h, b1, nullptr, ff2h, nullptr, ffph, nullptr, nullptr,
        MR, DI, DD, DIP);

    // 7. out = hn + ffp @ w3^T + b3                [4096 x 1024], K=2752
    gemm_tc_kernel<1><<<dim3(DD / GBN, MR / GBM), 256, GEMM_SMEM_BYTES>>>(
        ffph, w3h, b3, hn, nullptr, out, nullptr, nullptr, nullptr,
        MR, DD, DIP, DD);
}

// round 16
// speedup vs baseline: 1.0531x; 1.0175x over previous
#include <cuda_runtime.h>
#include <cuda_fp16.h>
#include <math.h>
#include <stdint.h>

// Problem constants
#define BB 2
#define SS 2048
#define DD 1024
#define HH 16
#define HD 64
#define DI 2730
#define DIP 2752           // DI padded to multiple of 64
#define MR 4096            // B*S rows
#define QKVLD (3 * DD)     // 3072
#define EPSV 1e-5f

// ---------------- scratch (device globals; no allocation allowed) ------------
// fp16 pad columns of g_ffph / g_ff2h / g_w3h (DI..DIP) stay zero: zero-init,
// never written.
__device__ float g_xn [MR * DD];
__device__ half  g_xnh[MR * DD];
__device__ half  g_qkvh[MR * QKVLD];
__device__ half  g_oh [MR * DD];
__device__ float g_h  [MR * DD];
__device__ float g_hn [MR * DD];
__device__ half  g_hnh[MR * DD];
__device__ half  g_ff2h[MR * DIP];
__device__ half  g_ffph[MR * DIP];
__device__ float g_cost[SS * 32];
__device__ float g_sint[SS * 32];
// fp16 weights
__device__ half  g_wqh[3 * DD * DD];
__device__ half  g_woh[DD * DD];
__device__ half  g_w1h[DI * DD];
__device__ half  g_w2h[DI * DD];
__device__ half  g_w3h[DD * DIP];

// ---------------- helpers ----------------------------------------------------
__device__ __forceinline__ void mma_f16(float* c, const uint32_t* a, const uint32_t* b) {
    asm volatile(
        "mma.sync.aligned.m16n8k16.row.col.f32.f16.f16.f32 "
        "{%0,%1,%2,%3},{%4,%5,%6,%7},{%8,%9},{%0,%1,%2,%3};"
        : "+f"(c[0]), "+f"(c[1]), "+f"(c[2]), "+f"(c[3])
        : "r"(a[0]), "r"(a[1]), "r"(a[2]), "r"(a[3]), "r"(b[0]), "r"(b[1]));
}

__device__ __forceinline__ void ldsm_x4(uint32_t* r, uint32_t addr) {
    asm volatile("ldmatrix.sync.aligned.m8n8.x4.shared.b16 {%0,%1,%2,%3}, [%4];"
                 : "=r"(r[0]), "=r"(r[1]), "=r"(r[2]), "=r"(r[3]) : "r"(addr));
}
__device__ __forceinline__ void ldsm_x2(uint32_t* r, uint32_t addr) {
    asm volatile("ldmatrix.sync.aligned.m8n8.x2.shared.b16 {%0,%1}, [%2];"
                 : "=r"(r[0]), "=r"(r[1]) : "r"(addr));
}

__device__ __forceinline__ void cp_async16(uint32_t dst, const void* src, int szbytes) {
    asm volatile("cp.async.ca.shared.global [%0], [%1], 16, %2;"
                 :: "r"(dst), "l"(src), "r"(szbytes));
}
__device__ __forceinline__ void cp_commit() {
    asm volatile("cp.async.commit_group;");
}
template <int N>
__device__ __forceinline__ void cp_wait() {
    asm volatile("cp.async.wait_group %0;" :: "n"(N));
}

// raw ex2 (single MUFU, no scaling FMA)
__device__ __forceinline__ float ex2(float x) {
    float y;
    asm("ex2.approx.f32 %0, %1;" : "=f"(y) : "f"(x));
    return y;
}

// ---------------- rmsnorm: fp32 + fp16 outputs -------------------------------
__global__ void rmsnorm_kernel(const float* __restrict__ X,
                               const float* __restrict__ gamma,
                               float* __restrict__ Y,
                               half* __restrict__ Yh)
{
    const int row = blockIdx.x;
    const float4* xr = (const float4*)(X + (size_t)row * DD);
    const float4* gm = (const float4*)gamma;
    float4*       yr = (float4*)(Y + (size_t)row * DD);

    const int t = threadIdx.x;
    float4 v = xr[t];
    float s = v.x * v.x + v.y * v.y + v.z * v.z + v.w * v.w;
    #pragma unroll
    for (int o = 16; o > 0; o >>= 1) s += __shfl_xor_sync(0xffffffffu, s, o);

    __shared__ float red[8];
    __shared__ float rinv_sh;
    if ((t & 31) == 0) red[t >> 5] = s;
    __syncthreads();
    if (t == 0) {
        float tt = 0.f;
        #pragma unroll
        for (int i = 0; i < 8; i++) tt += red[i];
        rinv_sh = rsqrtf(tt * (1.0f / DD) + EPSV);
    }
    __syncthreads();
    const float rinv = rinv_sh;
    float4 g = gm[t];
    float4 r = make_float4(v.x * rinv * g.x, v.y * rinv * g.y,
                           v.z * rinv * g.z, v.w * rinv * g.w);
    yr[t] = r;
    half* yh = Yh + (size_t)row * DD + t * 4;
    *(half2*)(yh)     = __floats2half2_rn(r.x, r.y);
    *(half2*)(yh + 2) = __floats2half2_rn(r.z, r.w);
}

// ---------------- fused prep: all weight cvts + w3 pad + rope tables ---------
#define PQ  (3 * DD * DD / 4)
#define PO  (DD * DD / 4)
#define P1  (DI * DD / 4)
#define P2  (DI * DD / 4)
#define P3  (DD * DIP / 4)
#define PT  (SS * 32 / 4)
#define PREP_TOTAL (PQ + PO + P1 + P2 + P3 + PT)

__global__ void prep_kernel(const float* __restrict__ w_qkv, const float* __restrict__ w_out,
                            const float* __restrict__ w1, const float* __restrict__ w2,
                            const float* __restrict__ w3,
                            half* __restrict__ wqh, half* __restrict__ woh,
                            half* __restrict__ w1h, half* __restrict__ w2h,
                            half* __restrict__ w3h,
                            float* __restrict__ cost, float* __restrict__ sint)
{
    int idx = blockIdx.x * 256 + threadIdx.x;
    if (idx >= PREP_TOTAL) return;

    if (idx < PQ + PO + P1 + P2) {
        const float* S; half* H; int i = idx;
        if (i < PQ)                { S = w_qkv; H = wqh; }
        else if ((i -= PQ) < PO)   { S = w_out; H = woh; }
        else if ((i -= PO) < P1)   { S = w1;    H = w1h; }
        else                       { i -= P1; S = w2; H = w2h; }
        float4 v = ((const float4*)S)[i];
        *(half2*)(H + (size_t)i * 4)     = __floats2half2_rn(v.x, v.y);
        *(half2*)(H + (size_t)i * 4 + 2) = __floats2half2_rn(v.z, v.w);
    } else if (idx < PQ + PO + P1 + P2 + P3) {
        int i = idx - (PQ + PO + P1 + P2);
        int base = i * 4;
        int row = base / DIP, col = base % DIP;
        #pragma unroll
        for (int e = 0; e < 4; e++) {
            int c = col + e;
            float x = (c < DI) ? w3[(size_t)row * DI + c] : 0.f;
            w3h[(size_t)row * DIP + c] = __float2half_rn(x);
        }
    } else {
        int i = (idx - (PQ + PO + P1 + P2 + P3)) * 4;
        #pragma unroll
        for (int e = 0; e < 4; e++) {
            int id = i + e;
            int ii = id & 31, s = id >> 5;
            float theta = powf(10000.f, -(float)ii / 32.f);
            float sn, cs;
            sincosf((float)s * theta, &sn, &cs);
            cost[id] = cs;
            sint[id] = sn;
        }
    }
}

// ---------------- fp16 tensor-core GEMM: C = A[M,K] * B[N,K]^T (+ epilogue)
// CTA 128x128x64(halves), 256 threads (8 warps 2x4, warp tile 64x32),
// cp.async 2-stage, ldmatrix fragment loads. Operands fp16, accum fp32.
// MODE 1: C  = z + bias + res                (fp32)
// MODE 2: Ch = half(silu(z + bias))          (fp16 out)
// MODE 3: Ch = half((z + bias) * resh)       (fp16 out, fp16 res)
// MODE 4: Ch = half(rope(z + bias))          (fp16 qkv out)
#define GBM 128
#define GBN 128
#define GBK 64                          // halves per K-tile
#define GLDSH 72                        // smem row stride in halves (+8 pad)
#define ASTG (GBM * GLDSH)              // halves per A stage
#define BSTG (GBN * GLDSH)
#define GEMM_SMEM_BYTES (2 * (ASTG + BSTG) * 2)    // 73728

template <int MODE>
__global__ __launch_bounds__(256, 2)
void gemm_tc_kernel(const half* __restrict__ A,
                    const half* __restrict__ Bm,
                    const float* __restrict__ bias,
                    const float* __restrict__ res,
                    const half* __restrict__ resh,
                    float* __restrict__ C,
                    half* __restrict__ Ch,
                    const float* __restrict__ cost,
                    const float* __restrict__ sint,
                    int M, int N, int K, int ldc)
{
    extern __shared__ half hsmem[];
    half* Asm = hsmem;                      // [2][GBM][GLDSH]
    half* Bsm = hsmem + 2 * ASTG;           // [2][GBN][GLDSH]

    const int tid = threadIdx.x;
    const int m0 = blockIdx.y * GBM;
    const int n0 = blockIdx.x * GBN;

    const int loadRow   = tid >> 3;         // 0..31
    const int loadChunk = (tid & 7) * 8;    // halves: 0,8,...,56

    const uint32_t aSmBase = (uint32_t)__cvta_generic_to_shared(Asm) +
                             (uint32_t)((loadRow * GLDSH + loadChunk) * 2);
    const uint32_t bSmBase = (uint32_t)__cvta_generic_to_shared(Bsm) +
                             (uint32_t)((loadRow * GLDSH + loadChunk) * 2);

    const int wid  = tid >> 5;
    const int lane = tid & 31;
    const int wm = (wid >> 2) * 64;         // 0 / 64
    const int wn = (wid & 3) * 32;          // 0 / 32 / 64 / 96
    const int tg = lane >> 2;               // 0..7
    const int tq = lane & 3;                // 0..3

    // ldmatrix lane addressing (halves)
    const int aLaneOff = (wm + (lane & 15)) * GLDSH + (lane >> 4) * 8;
    const int bLaneOff = (wn + (lane & 7)) * GLDSH + ((lane >> 3) & 1) * 8;
    const uint32_t aSmLd = (uint32_t)__cvta_generic_to_shared(Asm) + (uint32_t)(aLaneOff * 2);
    const uint32_t bSmLd = (uint32_t)__cvta_generic_to_shared(Bsm) + (uint32_t)(bLaneOff * 2);

    float acc[4][4][4];
    #pragma unroll
    for (int i = 0; i < 4; i++)
        #pragma unroll
        for (int j = 0; j < 4; j++)
            #pragma unroll
            for (int e = 0; e < 4; e++) acc[i][j][e] = 0.f;

    const int KT = K / GBK;

    auto load_stage = [&](int s, int kt) {
        const int k0 = kt * GBK;
        const uint32_t aDst = aSmBase + (uint32_t)(s * ASTG * 2);
        const uint32_t bDst = bSmBase + (uint32_t)(s * BSTG * 2);
        #pragma unroll
        for (int i = 0; i < 4; i++) {
            int r = loadRow + 32 * i;
            const half* srcA = A + (size_t)(m0 + r) * K + (k0 + loadChunk);
            cp_async16(aDst + (uint32_t)(i * 32 * GLDSH * 2), srcA, 16);
            int gn = n0 + r;
            int ok = (gn < N);
            const half* srcB = Bm + (size_t)(ok ? gn : 0) * K + (k0 + loadChunk);
            cp_async16(bDst + (uint32_t)(i * 32 * GLDSH * 2), srcB, ok ? 16 : 0);
        }
    };

    load_stage(0, 0);
    cp_commit();

    for (int kt = 0; kt < KT; kt++) {
        const int s = kt & 1;
        if (kt + 1 < KT) {
            load_stage(s ^ 1, kt + 1);
            cp_commit();
            cp_wait<1>();
        } else {
            cp_wait<0>();
        }
        __syncthreads();

        const uint32_t aLd = aSmLd + (uint32_t)(s * ASTG * 2);
        const uint32_t bLd = bSmLd + (uint32_t)(s * BSTG * 2);

        #pragma unroll
        for (int kk = 0; kk < GBK; kk += 16) {
            uint32_t af[4][4], bf[4][2];
            #pragma unroll
            for (int ti = 0; ti < 4; ti++)
                ldsm_x4(af[ti], aLd + (uint32_t)((16 * ti * GLDSH + kk) * 2));
            #pragma unroll
            for (int tj = 0; tj < 4; tj++)
                ldsm_x2(bf[tj], bLd + (uint32_t)((8 * tj * GLDSH + kk) * 2));
            #pragma unroll
            for (int ti = 0; ti < 4; ti++)
                #pragma unroll
                for (int tj = 0; tj < 4; tj++)
                    mma_f16(acc[ti][tj], af[ti], bf[tj]);
        }
        __syncthreads();
    }

    // ------------- epilogue ---------------------------------------------------
    #pragma unroll
    for (int ti = 0; ti < 4; ti++) {
        const int r0 = m0 + wm + 16 * ti + tg;
        const int r1 = r0 + 8;
        #pragma unroll
        for (int tj = 0; tj < 4; tj++) {
            const int cc = n0 + wn + 8 * tj + 2 * tq;
            const float* c = acc[ti][tj];
            if (MODE == 4) {
                float z0 = c[0] + bias[cc];
                float z1 = c[1] + bias[cc + 1];
                float z2 = c[2] + bias[cc];
                float z3 = c[3] + bias[cc + 1];
                size_t row0 = (size_t)r0 * ldc;
                size_t row1 = (size_t)r1 * ldc;
                if (cc >= 2 * DD) {
                    *(half2*)&Ch[row0 + cc] = __floats2half2_rn(z0, z1);
                    *(half2*)&Ch[row1 + cc] = __floats2half2_rn(z2, z3);
                } else {
                    int i = (cc & 63) >> 1;
                    int basec = cc & ~63;
                    int s0 = r0 & (SS - 1);
                    int s1 = r1 & (SS - 1);
                    float cs0 = cost[s0 * 32 + i], sn0 = sint[s0 * 32 + i];
                    float cs1 = cost[s1 * 32 + i], sn1 = sint[s1 * 32 + i];
                    Ch[row0 + basec + i]      = __float2half_rn(z0 * cs0 - z1 * sn0);
                    Ch[row0 + basec + 32 + i] = __float2half_rn(z0 * sn0 + z1 * cs0);
                    Ch[row1 + basec + i]      = __float2half_rn(z2 * cs1 - z3 * sn1);
                    Ch[row1 + basec + 32 + i] = __float2half_rn(z2 * sn1 + z3 * cs1);
                }
            } else if (MODE == 3) {
                if (cc < N) {
                    size_t o0 = (size_t)r0 * ldc + cc;
                    size_t o1 = (size_t)r1 * ldc + cc;
                    float2 b2v = *(const float2*)&bias[cc];
                    float2 rv0 = __half22float2(*(const half2*)(resh + o0));
                    float2 rv1 = __half22float2(*(const half2*)(resh + o1));
                    *(half2*)(Ch + o0) = __floats2half2_rn((c[0] + b2v.x) * rv0.x,
                                                           (c[1] + b2v.y) * rv0.y);
                    *(half2*)(Ch + o1) = __floats2half2_rn((c[2] + b2v.x) * rv1.x,
                                                           (c[3] + b2v.y) * rv1.y);
                }
            } else if (MODE == 2) {
                if (cc < N) {
                    size_t o0 = (size_t)r0 * ldc + cc;
                    size_t o1 = (size_t)r1 * ldc + cc;
                    float2 b2v = *(const float2*)&bias[cc];
                    float z0 = c[0] + b2v.x, z1 = c[1] + b2v.y;
                    float z2 = c[2] + b2v.x, z3 = c[3] + b2v.y;
                    *(half2*)(Ch + o0) = __floats2half2_rn(z0 / (1.f + __expf(-z0)),
                                                           z1 / (1.f + __expf(-z1)));
                    *(half2*)(Ch + o1) = __floats2half2_rn(z2 / (1.f + __expf(-z2)),
                                                           z3 / (1.f + __expf(-z3)));
                }
            } else {
                #pragma unroll
                for (int e = 0; e < 2; e++) {
                    const int col = cc + e;
                    if (col < N) {
                        size_t o0 = (size_t)r0 * ldc + col;
                        size_t o1 = (size_t)r1 * ldc + col;
                        float z0 = c[e]     + bias[col];
                        float z1 = c[e + 2] + bias[col];
                        C[o0] = z0 + res[o0];
                        C[o1] = z1 + res[o1];
                    }
                }
            }
        }
    }
}

// ---------------- tensor-core fused causal attention -------------------------
// fp16 qkv in ([B,S,3D] stride 3072), fp16 O out. Softmax in log2 domain.
// K and V fragments loaded via ldmatrix (x4 / x2).
#define AQT 128
#define AKT 64
#define KHSTR 72
#define VSTR 72
#define ATTN_K_BYTES (2 * AKT * KHSTR * 2)
#define ATTN_V_BYTES (2 * HD * VSTR * 2)
#define ATTN_SMEM_BYTES (ATTN_K_BYTES + ATTN_V_BYTES)

__global__ __launch_bounds__(256, 2)
void attn_tc_kernel(const half* __restrict__ QKV,
                    half* __restrict__ O)
{
    extern __shared__ char smraw[];
    half* Ksm = (half*)smraw;
    half* Vsm = (half*)(smraw + ATTN_K_BYTES);

    const int bh = blockIdx.y;
    const int bidx = bh >> 4, hidx = bh & 15;
    const int qt = gridDim.x - 1 - blockIdx.x;   // heaviest tiles first
    const int m0 = qt * AQT;

    const half* Qb = QKV + (size_t)(bidx * SS) * QKVLD + hidx * HD;
    const half* Kb = Qb + DD;
    const half* Vb = Qb + 2 * DD;

    const int tid  = threadIdx.x;
    const int wid  = tid >> 5;
    const int lane = tid & 31;
    const int tg   = lane >> 2;
    const int tq   = lane & 3;

    const int r0 = m0 + wid * 16 + tg;
    const int r1 = r0 + 8;

    // ldmatrix lane addressing into K / V tiles (halves)
    const uint32_t kSmLd = (uint32_t)__cvta_generic_to_shared(Ksm) +
                           (uint32_t)(((lane & 7) * KHSTR + (lane >> 3) * 8) * 2);       // x4
    const uint32_t vSmLd = (uint32_t)__cvta_generic_to_shared(Vsm) +
                           (uint32_t)(((lane & 7) * VSTR + ((lane >> 3) & 1) * 8) * 2);  // x2

    // Q fragments scaled by log2(e)/8 (log2-domain softmax)
    uint32_t qf[4][4];
    {
        const half2 scale = __half2half2(__float2half(0.18033688f));
        const half* q0 = Qb + (size_t)r0 * QKVLD;
        const half* q1 = q0 + 8 * QKVLD;
        #pragma unroll
        for (int kc = 0; kc < 4; kc++) {
            half2 h0 = __hmul2(*(const half2*)(q0 + kc * 16 + 2 * tq), scale);
            half2 h1 = __hmul2(*(const half2*)(q1 + kc * 16 + 2 * tq), scale);
            half2 h2 = __hmul2(*(const half2*)(q0 + kc * 16 + 2 * tq + 8), scale);
            half2 h3 = __hmul2(*(const half2*)(q1 + kc * 16 + 2 * tq + 8), scale);
            qf[kc][0] = *(uint32_t*)&h0;
            qf[kc][1] = *(uint32_t*)&h1;
            qf[kc][2] = *(uint32_t*)&h2;
            qf[kc][3] = *(uint32_t*)&h3;
        }
    }

    float oacc[8][4];
    #pragma unroll
    for (int dt = 0; dt < 8; dt++)
        #pragma unroll
        for (int e = 0; e < 4; e++) oacc[dt][e] = 0.f;
    float mrow0 = -1e30f, mrow1 = -1e30f, lrow0 = 0.f, lrow1 = 0.f;

    auto load_stage = [&](int st, int kt) {
        const int n0 = kt * AKT;
        {
            half* kdst = Ksm + st * AKT * KHSTR;
            int j  = tid >> 2;
            int d0 = (tid & 3) * 16;
            const half* krow = Kb + (size_t)(n0 + j) * QKVLD + d0;
            *(uint4*)(kdst + j * KHSTR + d0)     = *(const uint4*)(krow);
            *(uint4*)(kdst + j * KHSTR + d0 + 8) = *(const uint4*)(krow + 8);
        }
        {
            half* vdst = Vsm + st * HD * VSTR;
            const int d0  = tid & 31;
            const int jp0 = tid >> 5;
            #pragma unroll
            for (int ii = 0; ii < 4; ii++) {
                int jp = jp0 + 8 * ii;
                #pragma unroll
                for (int dd = 0; dd < 2; dd++) {
                    int d = d0 + 32 * dd;
                    half a = Vb[(size_t)(n0 + 2 * jp)     * QKVLD + d];
                    half b = Vb[(size_t)(n0 + 2 * jp + 1) * QKVLD + d];
                    *(half2*)(vdst + d * VSTR + 2 * jp) = __halves2half2(a, b);
                }
            }
        }
    };

    load_stage(0, 0);

    const int ktend = 2 * qt + 1;
    for (int kt = 0; kt <= ktend; kt++) {
        const int s = kt & 1;
        const int n0 = kt * AKT;
        __syncthreads();
        if (kt < ktend) load_stage(s ^ 1, kt + 1);

        const uint32_t kLd = kSmLd + (uint32_t)(s * AKT * KHSTR * 2);
        const uint32_t vLd = vSmLd + (uint32_t)(s * HD * VSTR * 2);

        // ---- scores = Q @ K^T (K frags via ldmatrix.x4) ------------------------
        float sc[8][4];
        #pragma unroll
        for (int nt = 0; nt < 8; nt++) {
            #pragma unroll
            for (int e = 0; e < 4; e++) sc[nt][e] = 0.f;
            #pragma unroll
            for (int kc2 = 0; kc2 < 2; kc2++) {
                uint32_t kf4[4];
                ldsm_x4(kf4, kLd + (uint32_t)((nt * 8 * KHSTR + kc2 * 32) * 2));
                mma_f16(sc[nt], qf[2 * kc2],     kf4);
                mma_f16(sc[nt], qf[2 * kc2 + 1], kf4 + 2);
            }
        }

        if (kt >= 2 * qt) {
            #pragma unroll
            for (int nt = 0; nt < 8; nt++) {
                int jg = n0 + nt * 8 + 2 * tq;
                if (jg     > r0) sc[nt][0] = -1e30f;
                if (jg + 1 > r0) sc[nt][1] = -1e30f;
                if (jg     > r1) sc[nt][2] = -1e30f;
                if (jg + 1 > r1) sc[nt][3] = -1e30f;
            }
        }

        // ---- online softmax (log2 domain) --------------------------------------
        float tm0 = -1e30f, tm1 = -1e30f;
        #pragma unroll
        for (int nt = 0; nt < 8; nt++) {
            tm0 = fmaxf(tm0, fmaxf(sc[nt][0], sc[nt][1]));
            tm1 = fmaxf(tm1, fmaxf(sc[nt][2], sc[nt][3]));
        }
        tm0 = fmaxf(tm0, __shfl_xor_sync(0xffffffffu, tm0, 1));
        tm0 = fmaxf(tm0, __shfl_xor_sync(0xffffffffu, tm0, 2));
        tm1 = fmaxf(tm1, __shfl_xor_sync(0xffffffffu, tm1, 1));
        tm1 = fmaxf(tm1, __shfl_xor_sync(0xffffffffu, tm1, 2));

        float mn0 = fmaxf(mrow0, tm0), mn1 = fmaxf(mrow1, tm1);
        float al0 = ex2(mrow0 - mn0), al1 = ex2(mrow1 - mn1);
        mrow0 = mn0; mrow1 = mn1;

        float sum0 = 0.f, sum1 = 0.f;
        #pragma unroll
        for (int nt = 0; nt < 8; nt++) {
            sc[nt][0] = ex2(sc[nt][0] - mn0); sum0 += sc[nt][0];
            sc[nt][1] = ex2(sc[nt][1] - mn0); sum0 += sc[nt][1];
            sc[nt][2] = ex2(sc[nt][2] - mn1); sum1 += sc[nt][2];
            sc[nt][3] = ex2(sc[nt][3] - mn1); sum1 += sc[nt][3];
        }
        sum0 += __shfl_xor_sync(0xffffffffu, sum0, 1);
        sum0 += __shfl_xor_sync(0xffffffffu, sum0, 2);
        sum1 += __shfl_xor_sync(0xffffffffu, sum1, 1);
        sum1 += __shfl_xor_sync(0xffffffffu, sum1, 2);
        lrow0 = lrow0 * al0 + sum0;
        lrow1 = lrow1 * al1 + sum1;

        #pragma unroll
        for (int dt = 0; dt < 8; dt++) {
            oacc[dt][0] *= al0; oacc[dt][1] *= al0;
            oacc[dt][2] *= al1; oacc[dt][3] *= al1;
        }

        // ---- O += P @ V (V frags via ldmatrix.x2) -------------------------------
        #pragma unroll
        for (int kc = 0; kc < 4; kc++) {
            uint32_t pa[4];
            half2 p0 = __floats2half2_rn(sc[2 * kc][0],     sc[2 * kc][1]);
            half2 p1 = __floats2half2_rn(sc[2 * kc][2],     sc[2 * kc][3]);
            half2 p2 = __floats2half2_rn(sc[2 * kc + 1][0], sc[2 * kc + 1][1]);
            half2 p3 = __floats2half2_rn(sc[2 * kc + 1][2], sc[2 * kc + 1][3]);
            pa[0] = *(uint32_t*)&p0; pa[1] = *(uint32_t*)&p1;
            pa[2] = *(uint32_t*)&p2; pa[3] = *(uint32_t*)&p3;
            #pragma unroll
            for (int dt = 0; dt < 8; dt++) {
                uint32_t vb[2];
                ldsm_x2(vb, vLd + (uint32_t)((dt * 8 * VSTR + kc * 16) * 2));
                mma_f16(oacc[dt], pa, vb);
            }
        }
    }

    // ---- write O (fp16) in [B,S,D] ---------------------------------------------
    const float inv0 = 1.f / lrow0;
    const float inv1 = 1.f / lrow1;
    #pragma unroll
    for (int dt = 0; dt < 8; dt++) {
        int dcol = hidx * HD + dt * 8 + 2 * tq;
        *(half2*)&O[((size_t)(bidx * SS + r0)) * DD + dcol] =
            __floats2half2_rn(oacc[dt][0] * inv0, oacc[dt][1] * inv0);
        *(half2*)&O[((size_t)(bidx * SS + r1)) * DD + dcol] =
            __floats2half2_rn(oacc[dt][2] * inv1, oacc[dt][3] * inv1);
    }
}

// ---------------- launch -----------------------------------------------------
extern "C" void kernel_launch(void* const* d_in, const int* in_sizes, int n_in,
                              void* d_out, int out_size)
{
    const float* x          = (const float*)d_in[0];
    // d_in[1] = mask (unused — causal handled analytically)
    const float* gamma_attn = (const float*)d_in[2];
    const float* w_qkv      = (const float*)d_in[3];
    const float* b_qkv      = (const float*)d_in[4];
    const float* w_out      = (const float*)d_in[5];
    const float* b_out      = (const float*)d_in[6];
    const float* gamma_ffn  = (const float*)d_in[7];
    const float* w1         = (const float*)d_in[8];
    const float* b1         = (const float*)d_in[9];
    const float* w2         = (const float*)d_in[10];
    const float* b2         = (const float*)d_in[11];
    const float* w3         = (const float*)d_in[12];
    const float* b3         = (const float*)d_in[13];
    float* out = (float*)d_out;

    float *xn, *h, *hn, *cost, *sint;
    half *xnh, *qkvh, *oh, *hnh, *ff2h, *ffph, *wqh, *woh, *w1h, *w2h, *w3h;
    cudaGetSymbolAddress((void**)&xn,   g_xn);
    cudaGetSymbolAddress((void**)&xnh,  g_xnh);
    cudaGetSymbolAddress((void**)&qkvh, g_qkvh);
    cudaGetSymbolAddress((void**)&oh,   g_oh);
    cudaGetSymbolAddress((void**)&h,    g_h);
    cudaGetSymbolAddress((void**)&hn,   g_hn);
    cudaGetSymbolAddress((void**)&hnh,  g_hnh);
    cudaGetSymbolAddress((void**)&ff2h, g_ff2h);
    cudaGetSymbolAddress((void**)&ffph, g_ffph);
    cudaGetSymbolAddress((void**)&cost, g_cost);
    cudaGetSymbolAddress((void**)&sint, g_sint);
    cudaGetSymbolAddress((void**)&wqh,  g_wqh);
    cudaGetSymbolAddress((void**)&woh,  g_woh);
    cudaGetSymbolAddress((void**)&w1h,  g_w1h);
    cudaGetSymbolAddress((void**)&w2h,  g_w2h);
    cudaGetSymbolAddress((void**)&w3h,  g_w3h);

    cudaFuncSetAttribute(attn_tc_kernel, cudaFuncAttributeMaxDynamicSharedMemorySize,
                         ATTN_SMEM_BYTES);
    cudaFuncSetAttribute(gemm_tc_kernel<1>, cudaFuncAttributeMaxDynamicSharedMemorySize,
                         GEMM_SMEM_BYTES);
    cudaFuncSetAttribute(gemm_tc_kernel<2>, cudaFuncAttributeMaxDynamicSharedMemorySize,
                         GEMM_SMEM_BYTES);
    cudaFuncSetAttribute(gemm_tc_kernel<3>, cudaFuncAttributeMaxDynamicSharedMemorySize,
                         GEMM_SMEM_BYTES);
    cudaFuncSetAttribute(gemm_tc_kernel<4>, cudaFuncAttributeMaxDynamicSharedMemorySize,
                         GEMM_SMEM_BYTES);

    // 0. fused prep: weight fp16 conversions + w3 pad + rope tables
    prep_kernel<<<(PREP_TOTAL + 255) / 256, 256>>>(
        w_qkv, w_out, w1, w2, w3, wqh, woh, w1h, w2h, w3h, cost, sint);

    // 1. xn = rmsnorm(x, gamma_attn)  (fp32 + fp16)
    rmsnorm_kernel<<<MR, 256>>>(x, gamma_attn, xn, xnh);

    // 2. qkvh = half(rope(xn @ w_qkv^T + b_qkv))   [4096 x 3072], K=1024
    gemm_tc_kernel<4><<<dim3(QKVLD / GBN, MR / GBM), 256, GEMM_SMEM_BYTES>>>(
        xnh, wqh, b_qkv, nullptr, nullptr, nullptr, qkvh, cost, sint,
        MR, QKVLD, DD, QKVLD);

    // 3. fused causal attention (fp16 qkv) -> oh fp16 in [B,S,D]
    attn_tc_kernel<<<dim3(SS / AQT, BB * HH), 256, ATTN_SMEM_BYTES>>>(qkvh, oh);

    // 4. h = xn + o @ w_out^T + b_out              [4096 x 1024], K=1024
    gemm_tc_kernel<1><<<dim3(DD / GBN, MR / GBM), 256, GEMM_SMEM_BYTES>>>(
        oh, woh, b_out, xn, nullptr, h, nullptr, nullptr, nullptr,
        MR, DD, DD, DD);

    // 5. hn = rmsnorm(h, gamma_ffn)  (fp32 + fp16)
    rmsnorm_kernel<<<MR, 256>>>(h, gamma_ffn, hn, hnh);

    // 6a. ff2h = half(silu(hn @ w2^T + b2))        [4096 x 2730] @ ldc DIP
    gemm_tc_kernel<2><<<dim3((DI + GBN - 1) / GBN, MR / GBM), 256, GEMM_SMEM_BYTES>>>(
        hnh, w2h, b2, nullptr, nullptr, nullptr, ff2h, nullptr, nullptr,
        MR, DI, DD, DIP);

    // 6b. ffph = half((hn @ w1^T + b1) * ff2h)     [4096 x 2730] @ ldc DIP
    gemm_tc_kernel<3><<<dim3((DI + GBN - 1) / GBN, MR / GBM), 256, GEMM_SMEM_BYTES>>>(
        hnh, w1h, b1, nullptr, ff2h, nullptr, ffph, nullptr, nullptr,
        MR, DI, DD, DIP);

    // 7. out = hn + ffp @ w3^T + b3                [4096 x 1024], K=2752
    gemm_tc_kernel<1><<<dim3(DD / GBN, MR / GBM), 256, GEMM_SMEM_BYTES>>>(
        ffph, w3h, b3, hn, nullptr, out, nullptr, nullptr, nullptr,
        MR, DD, DIP, DD);
}

// round 17
// speedup vs baseline: 1.0794x; 1.0249x over previous
#include <cuda_runtime.h>
#include <cuda_fp16.h>
#include <math.h>
#include <stdint.h>

// Problem constants
#define BB 2
#define SS 2048
#define DD 1024
#define HH 16
#define HD 64
#define DI 2730
#define DIP 2752           // DI padded to multiple of 64
#define MR 4096            // B*S rows
#define QKVLD (3 * DD)     // 3072
#define EPSV 1e-5f

// ---------------- scratch (device globals; no allocation allowed) ------------
// fp16 pad columns of g_ffph / g_w3h (DI..DIP) stay zero: zero-init, never written.
__device__ float g_xn [MR * DD];
__device__ half  g_xnh[MR * DD];
__device__ half  g_qkvh[MR * QKVLD];
__device__ half  g_oh [MR * DD];
__device__ float g_h  [MR * DD];
__device__ float g_hn [MR * DD];
__device__ half  g_hnh[MR * DD];
__device__ half  g_ffph[MR * DIP];
__device__ float g_cost[SS * 32];
__device__ float g_sint[SS * 32];
// fp16 weights
__device__ half  g_wqh[3 * DD * DD];
__device__ half  g_woh[DD * DD];
__device__ half  g_w1h[DI * DD];
__device__ half  g_w2h[DI * DD];
__device__ half  g_w3h[DD * DIP];

// ---------------- helpers ----------------------------------------------------
__device__ __forceinline__ void mma_f16(float* c, const uint32_t* a, const uint32_t* b) {
    asm volatile(
        "mma.sync.aligned.m16n8k16.row.col.f32.f16.f16.f32 "
        "{%0,%1,%2,%3},{%4,%5,%6,%7},{%8,%9},{%0,%1,%2,%3};"
        : "+f"(c[0]), "+f"(c[1]), "+f"(c[2]), "+f"(c[3])
        : "r"(a[0]), "r"(a[1]), "r"(a[2]), "r"(a[3]), "r"(b[0]), "r"(b[1]));
}

__device__ __forceinline__ void ldsm_x4(uint32_t* r, uint32_t addr) {
    asm volatile("ldmatrix.sync.aligned.m8n8.x4.shared.b16 {%0,%1,%2,%3}, [%4];"
                 : "=r"(r[0]), "=r"(r[1]), "=r"(r[2]), "=r"(r[3]) : "r"(addr));
}
__device__ __forceinline__ void ldsm_x2(uint32_t* r, uint32_t addr) {
    asm volatile("ldmatrix.sync.aligned.m8n8.x2.shared.b16 {%0,%1}, [%2];"
                 : "=r"(r[0]), "=r"(r[1]) : "r"(addr));
}

__device__ __forceinline__ void cp_async16(uint32_t dst, const void* src, int szbytes) {
    asm volatile("cp.async.ca.shared.global [%0], [%1], 16, %2;"
                 :: "r"(dst), "l"(src), "r"(szbytes));
}
__device__ __forceinline__ void cp_commit() {
    asm volatile("cp.async.commit_group;");
}
template <int N>
__device__ __forceinline__ void cp_wait() {
    asm volatile("cp.async.wait_group %0;" :: "n"(N));
}

// raw ex2 (single MUFU, no scaling FMA)
__device__ __forceinline__ float ex2(float x) {
    float y;
    asm("ex2.approx.f32 %0, %1;" : "=f"(y) : "f"(x));
    return y;
}

// ---------------- rmsnorm: fp32 + fp16 outputs -------------------------------
__global__ void rmsnorm_kernel(const float* __restrict__ X,
                               const float* __restrict__ gamma,
                               float* __restrict__ Y,
                               half* __restrict__ Yh)
{
    const int row = blockIdx.x;
    const float4* xr = (const float4*)(X + (size_t)row * DD);
    const float4* gm = (const float4*)gamma;
    float4*       yr = (float4*)(Y + (size_t)row * DD);

    const int t = threadIdx.x;
    float4 v = xr[t];
    float s = v.x * v.x + v.y * v.y + v.z * v.z + v.w * v.w;
    #pragma unroll
    for (int o = 16; o > 0; o >>= 1) s += __shfl_xor_sync(0xffffffffu, s, o);

    __shared__ float red[8];
    __shared__ float rinv_sh;
    if ((t & 31) == 0) red[t >> 5] = s;
    __syncthreads();
    if (t == 0) {
        float tt = 0.f;
        #pragma unroll
        for (int i = 0; i < 8; i++) tt += red[i];
        rinv_sh = rsqrtf(tt * (1.0f / DD) + EPSV);
    }
    __syncthreads();
    const float rinv = rinv_sh;
    float4 g = gm[t];
    float4 r = make_float4(v.x * rinv * g.x, v.y * rinv * g.y,
                           v.z * rinv * g.z, v.w * rinv * g.w);
    yr[t] = r;
    half* yh = Yh + (size_t)row * DD + t * 4;
    *(half2*)(yh)     = __floats2half2_rn(r.x, r.y);
    *(half2*)(yh + 2) = __floats2half2_rn(r.z, r.w);
}

// ---------------- fused prep: all weight cvts + w3 pad + rope tables ---------
#define PQ  (3 * DD * DD / 4)
#define PO  (DD * DD / 4)
#define P1  (DI * DD / 4)
#define P2  (DI * DD / 4)
#define P3  (DD * DIP / 4)
#define PT  (SS * 32 / 4)
#define PREP_TOTAL (PQ + PO + P1 + P2 + P3 + PT)

__global__ void prep_kernel(const float* __restrict__ w_qkv, const float* __restrict__ w_out,
                            const float* __restrict__ w1, const float* __restrict__ w2,
                            const float* __restrict__ w3,
                            half* __restrict__ wqh, half* __restrict__ woh,
                            half* __restrict__ w1h, half* __restrict__ w2h,
                            half* __restrict__ w3h,
                            float* __restrict__ cost, float* __restrict__ sint)
{
    int idx = blockIdx.x * 256 + threadIdx.x;
    if (idx >= PREP_TOTAL) return;

    if (idx < PQ + PO + P1 + P2) {
        const float* S; half* H; int i = idx;
        if (i < PQ)                { S = w_qkv; H = wqh; }
        else if ((i -= PQ) < PO)   { S = w_out; H = woh; }
        else if ((i -= PO) < P1)   { S = w1;    H = w1h; }
        else                       { i -= P1; S = w2; H = w2h; }
        float4 v = ((const float4*)S)[i];
        *(half2*)(H + (size_t)i * 4)     = __floats2half2_rn(v.x, v.y);
        *(half2*)(H + (size_t)i * 4 + 2) = __floats2half2_rn(v.z, v.w);
    } else if (idx < PQ + PO + P1 + P2 + P3) {
        int i = idx - (PQ + PO + P1 + P2);
        int base = i * 4;
        int row = base / DIP, col = base % DIP;
        #pragma unroll
        for (int e = 0; e < 4; e++) {
            int c = col + e;
            float x = (c < DI) ? w3[(size_t)row * DI + c] : 0.f;
            w3h[(size_t)row * DIP + c] = __float2half_rn(x);
        }
    } else {
        int i = (idx - (PQ + PO + P1 + P2 + P3)) * 4;
        #pragma unroll
        for (int e = 0; e < 4; e++) {
            int id = i + e;
            int ii = id & 31, s = id >> 5;
            float theta = powf(10000.f, -(float)ii / 32.f);
            float sn, cs;
            sincosf((float)s * theta, &sn, &cs);
            cost[id] = cs;
            sint[id] = sn;
        }
    }
}

// ---------------- fp16 tensor-core GEMM: C = A[M,K] * B[N,K]^T (+ epilogue)
// CTA 128x128x64(halves), 256 threads (8 warps 2x4, warp tile 64x32),
// cp.async 2-stage, ldmatrix fragment loads. Operands fp16, accum fp32.
// MODE 1: C  = z + bias + res                (fp32; N even, vectorized)
// MODE 4: Ch = half(rope(z + bias))          (fp16 qkv out)
#define GBM 128
#define GBN 128
#define GBK 64                          // halves per K-tile
#define GLDSH 72                        // smem row stride in halves (+8 pad)
#define ASTG (GBM * GLDSH)              // halves per A stage
#define BSTG (GBN * GLDSH)
#define GEMM_SMEM_BYTES (2 * (ASTG + BSTG) * 2)    // 73728

template <int MODE>
__global__ __launch_bounds__(256, 2)
void gemm_tc_kernel(const half* __restrict__ A,
                    const half* __restrict__ Bm,
                    const float* __restrict__ bias,
                    const float* __restrict__ res,
                    float* __restrict__ C,
                    half* __restrict__ Ch,
                    const float* __restrict__ cost,
                    const float* __restrict__ sint,
                    int M, int N, int K, int ldc)
{
    extern __shared__ half hsmem[];
    half* Asm = hsmem;                      // [2][GBM][GLDSH]
    half* Bsm = hsmem + 2 * ASTG;           // [2][GBN][GLDSH]

    const int tid = threadIdx.x;
    const int m0 = blockIdx.y * GBM;
    const int n0 = blockIdx.x * GBN;

    const int loadRow   = tid >> 3;         // 0..31
    const int loadChunk = (tid & 7) * 8;    // halves: 0,8,...,56

    const uint32_t aSmBase = (uint32_t)__cvta_generic_to_shared(Asm) +
                             (uint32_t)((loadRow * GLDSH + loadChunk) * 2);
    const uint32_t bSmBase = (uint32_t)__cvta_generic_to_shared(Bsm) +
                             (uint32_t)((loadRow * GLDSH + loadChunk) * 2);

    const int wid  = tid >> 5;
    const int lane = tid & 31;
    const int wm = (wid >> 2) * 64;         // 0 / 64
    const int wn = (wid & 3) * 32;          // 0 / 32 / 64 / 96
    const int tg = lane >> 2;               // 0..7
    const int tq = lane & 3;                // 0..3

    // ldmatrix lane addressing (halves)
    const int aLaneOff = (wm + (lane & 15)) * GLDSH + (lane >> 4) * 8;
    const int bLaneOff = (wn + (lane & 7)) * GLDSH + ((lane >> 3) & 1) * 8;
    const uint32_t aSmLd = (uint32_t)__cvta_generic_to_shared(Asm) + (uint32_t)(aLaneOff * 2);
    const uint32_t bSmLd = (uint32_t)__cvta_generic_to_shared(Bsm) + (uint32_t)(bLaneOff * 2);

    float acc[4][4][4];
    #pragma unroll
    for (int i = 0; i < 4; i++)
        #pragma unroll
        for (int j = 0; j < 4; j++)
            #pragma unroll
            for (int e = 0; e < 4; e++) acc[i][j][e] = 0.f;

    const int KT = K / GBK;

    auto load_stage = [&](int s, int kt) {
        const int k0 = kt * GBK;
        const uint32_t aDst = aSmBase + (uint32_t)(s * ASTG * 2);
        const uint32_t bDst = bSmBase + (uint32_t)(s * BSTG * 2);
        #pragma unroll
        for (int i = 0; i < 4; i++) {
            int r = loadRow + 32 * i;
            const half* srcA = A + (size_t)(m0 + r) * K + (k0 + loadChunk);
            cp_async16(aDst + (uint32_t)(i * 32 * GLDSH * 2), srcA, 16);
            int gn = n0 + r;
            int ok = (gn < N);
            const half* srcB = Bm + (size_t)(ok ? gn : 0) * K + (k0 + loadChunk);
            cp_async16(bDst + (uint32_t)(i * 32 * GLDSH * 2), srcB, ok ? 16 : 0);
        }
    };

    load_stage(0, 0);
    cp_commit();

    for (int kt = 0; kt < KT; kt++) {
        const int s = kt & 1;
        if (kt + 1 < KT) {
            load_stage(s ^ 1, kt + 1);
            cp_commit();
            cp_wait<1>();
        } else {
            cp_wait<0>();
        }
        __syncthreads();

        const uint32_t aLd = aSmLd + (uint32_t)(s * ASTG * 2);
        const uint32_t bLd = bSmLd + (uint32_t)(s * BSTG * 2);

        #pragma unroll
        for (int kk = 0; kk < GBK; kk += 16) {
            uint32_t af[4][4], bf[4][2];
            #pragma unroll
            for (int ti = 0; ti < 4; ti++)
                ldsm_x4(af[ti], aLd + (uint32_t)((16 * ti * GLDSH + kk) * 2));
            #pragma unroll
            for (int tj = 0; tj < 4; tj++)
                ldsm_x2(bf[tj], bLd + (uint32_t)((8 * tj * GLDSH + kk) * 2));
            #pragma unroll
            for (int ti = 0; ti < 4; ti++)
                #pragma unroll
                for (int tj = 0; tj < 4; tj++)
                    mma_f16(acc[ti][tj], af[ti], bf[tj]);
        }
        __syncthreads();
    }

    // ------------- epilogue ---------------------------------------------------
    #pragma unroll
    for (int ti = 0; ti < 4; ti++) {
        const int r0 = m0 + wm + 16 * ti + tg;
        const int r1 = r0 + 8;
        #pragma unroll
        for (int tj = 0; tj < 4; tj++) {
            const int cc = n0 + wn + 8 * tj + 2 * tq;
            const float* c = acc[ti][tj];
            if (MODE == 4) {
                float z0 = c[0] + bias[cc];
                float z1 = c[1] + bias[cc + 1];
                float z2 = c[2] + bias[cc];
                float z3 = c[3] + bias[cc + 1];
                size_t row0 = (size_t)r0 * ldc;
                size_t row1 = (size_t)r1 * ldc;
                if (cc >= 2 * DD) {
                    *(half2*)&Ch[row0 + cc] = __floats2half2_rn(z0, z1);
                    *(half2*)&Ch[row1 + cc] = __floats2half2_rn(z2, z3);
                } else {
                    int i = (cc & 63) >> 1;
                    int basec = cc & ~63;
                    int s0 = r0 & (SS - 1);
                    int s1 = r1 & (SS - 1);
                    float cs0 = cost[s0 * 32 + i], sn0 = sint[s0 * 32 + i];
                    float cs1 = cost[s1 * 32 + i], sn1 = sint[s1 * 32 + i];
                    Ch[row0 + basec + i]      = __float2half_rn(z0 * cs0 - z1 * sn0);
                    Ch[row0 + basec + 32 + i] = __float2half_rn(z0 * sn0 + z1 * cs0);
                    Ch[row1 + basec + i]      = __float2half_rn(z2 * cs1 - z3 * sn1);
                    Ch[row1 + basec + 32 + i] = __float2half_rn(z2 * sn1 + z3 * cs1);
                }
            } else {
                // MODE 1, N even: pair is entirely in or out
                if (cc < N) {
                    size_t o0 = (size_t)r0 * ldc + cc;
                    size_t o1 = (size_t)r1 * ldc + cc;
                    float2 bv  = *(const float2*)&bias[cc];
                    float2 rv0 = *(const float2*)&res[o0];
                    float2 rv1 = *(const float2*)&res[o1];
                    *(float2*)&C[o0] = make_float2(c[0] + bv.x + rv0.x, c[1] + bv.y + rv0.y);
                    *(float2*)&C[o1] = make_float2(c[2] + bv.x + rv1.x, c[3] + bv.y + rv1.y);
                }
            }
        }
    }
}

// ---------------- fused FFN dual-GEMM: ffp = (A@w1^T+b1) * silu(A@w2^T+b2) ---
// CTA computes a 128(M) x 64(N) slab of BOTH products. B-smem rows 0-63 <- w1,
// 64-127 <- w2 (same smem/mainloop shape as gemm_tc_kernel). Gate warps
// (wn>=64) push silu(z2) through a reused-smem fp32 exchange buffer.
#define FFN_EXSTR 34     // float2 row stride of exchange buffer (68 floats)

__global__ __launch_bounds__(256, 2)
void gemm_ffn_kernel(const half* __restrict__ A,
                     const half* __restrict__ B1,
                     const half* __restrict__ B2,
                     const float* __restrict__ b1,
                     const float* __restrict__ b2,
                     half* __restrict__ Ch,
                     int M, int N, int K, int ldc)
{
    extern __shared__ half hsmem[];
    half* Asm = hsmem;
    half* Bsm = hsmem + 2 * ASTG;
    float2* exbuf = (float2*)hsmem;         // reused after mainloop: [128][FFN_EXSTR]

    const int tid = threadIdx.x;
    const int m0 = blockIdx.y * GBM;
    const int n0 = blockIdx.x * 64;

    const int loadRow   = tid >> 3;
    const int loadChunk = (tid & 7) * 8;

    const uint32_t aSmBase = (uint32_t)__cvta_generic_to_shared(Asm) +
                             (uint32_t)((loadRow * GLDSH + loadChunk) * 2);
    const uint32_t bSmBase = (uint32_t)__cvta_generic_to_shared(Bsm) +
                             (uint32_t)((loadRow * GLDSH + loadChunk) * 2);

    const int wid  = tid >> 5;
    const int lane = tid & 31;
    const int wm = (wid >> 2) * 64;
    const int wn = (wid & 3) * 32;          // 0/32: w1 cols, 64/96: w2 cols
    const int tg = lane >> 2;
    const int tq = lane & 3;

    const int aLaneOff = (wm + (lane & 15)) * GLDSH + (lane >> 4) * 8;
    const int bLaneOff = (wn + (lane & 7)) * GLDSH + ((lane >> 3) & 1) * 8;
    const uint32_t aSmLd = (uint32_t)__cvta_generic_to_shared(Asm) + (uint32_t)(aLaneOff * 2);
    const uint32_t bSmLd = (uint32_t)__cvta_generic_to_shared(Bsm) + (uint32_t)(bLaneOff * 2);

    float acc[4][4][4];
    #pragma unroll
    for (int i = 0; i < 4; i++)
        #pragma unroll
        for (int j = 0; j < 4; j++)
            #pragma unroll
            for (int e = 0; e < 4; e++) acc[i][j][e] = 0.f;

    const int KT = K / GBK;

    auto load_stage = [&](int s, int kt) {
        const int k0 = kt * GBK;
        const uint32_t aDst = aSmBase + (uint32_t)(s * ASTG * 2);
        const uint32_t bDst = bSmBase + (uint32_t)(s * BSTG * 2);
        #pragma unroll
        for (int i = 0; i < 4; i++) {
            int r = loadRow + 32 * i;
            const half* srcA = A + (size_t)(m0 + r) * K + (k0 + loadChunk);
            cp_async16(aDst + (uint32_t)(i * 32 * GLDSH * 2), srcA, 16);
            int gn = n0 + (r & 63);
            int ok = (gn < N);
            const half* srcB = ((r < 64) ? B1 : B2) + (size_t)(ok ? gn : 0) * K + (k0 + loadChunk);
            cp_async16(bDst + (uint32_t)(i * 32 * GLDSH * 2), srcB, ok ? 16 : 0);
        }
    };

    load_stage(0, 0);
    cp_commit();

    for (int kt = 0; kt < KT; kt++) {
        const int s = kt & 1;
        if (kt + 1 < KT) {
            load_stage(s ^ 1, kt + 1);
            cp_commit();
            cp_wait<1>();
        } else {
            cp_wait<0>();
        }
        __syncthreads();

        const uint32_t aLd = aSmLd + (uint32_t)(s * ASTG * 2);
        const uint32_t bLd = bSmLd + (uint32_t)(s * BSTG * 2);

        #pragma unroll
        for (int kk = 0; kk < GBK; kk += 16) {
            uint32_t af[4][4], bf[4][2];
            #pragma unroll
            for (int ti = 0; ti < 4; ti++)
                ldsm_x4(af[ti], aLd + (uint32_t)((16 * ti * GLDSH + kk) * 2));
            #pragma unroll
            for (int tj = 0; tj < 4; tj++)
                ldsm_x2(bf[tj], bLd + (uint32_t)((8 * tj * GLDSH + kk) * 2));
            #pragma unroll
            for (int ti = 0; ti < 4; ti++)
                #pragma unroll
                for (int tj = 0; tj < 4; tj++)
                    mma_f16(acc[ti][tj], af[ti], bf[tj]);
        }
        __syncthreads();
    }

    // ---- epilogue phase 1: gate warps write silu(z2) to exchange buffer ------
    if ((wid & 3) >= 2) {
        #pragma unroll
        for (int ti = 0; ti < 4; ti++) {
            const int rl0 = wm + 16 * ti + tg;     // local rows 0..127
            const int rl1 = rl0 + 8;
            #pragma unroll
            for (int tj = 0; tj < 4; tj++) {
                const int cl = (wn - 64) + 8 * tj + 2 * tq;   // local col 0..63
                const int cc = n0 + cl;
                if (cc < N) {
                    const float* c = acc[ti][tj];
                    float2 bv = *(const float2*)&b2[cc];
                    float z0 = c[0] + bv.x, z1 = c[1] + bv.y;
                    float z2 = c[2] + bv.x, z3 = c[3] + bv.y;
                    exbuf[rl0 * FFN_EXSTR + (cl >> 1)] =
                        make_float2(z0 / (1.f + __expf(-z0)), z1 / (1.f + __expf(-z1)));
                    exbuf[rl1 * FFN_EXSTR + (cl >> 1)] =
                        make_float2(z2 / (1.f + __expf(-z2)), z3 / (1.f + __expf(-z3)));
                }
            }
        }
    }
    __syncthreads();

    // ---- epilogue phase 2: value warps multiply and store fp16 ---------------
    if ((wid & 3) < 2) {
        #pragma unroll
        for (int ti = 0; ti < 4; ti++) {
            const int rl0 = wm + 16 * ti + tg;
            const int rl1 = rl0 + 8;
            const int r0 = m0 + rl0;
            const int r1 = m0 + rl1;
            #pragma unroll
            for (int tj = 0; tj < 4; tj++) {
                const int cl = wn + 8 * tj + 2 * tq;          // local col 0..63
                const int cc = n0 + cl;
                if (cc < N) {
                    const float* c = acc[ti][tj];
                    float2 bv = *(const float2*)&b1[cc];
                    float2 g0 = exbuf[rl0 * FFN_EXSTR + (cl >> 1)];
                    float2 g1 = exbuf[rl1 * FFN_EXSTR + (cl >> 1)];
                    *(half2*)(Ch + (size_t)r0 * ldc + cc) =
                        __floats2half2_rn((c[0] + bv.x) * g0.x, (c[1] + bv.y) * g0.y);
                    *(half2*)(Ch + (size_t)r1 * ldc + cc) =
                        __floats2half2_rn((c[2] + bv.x) * g1.x, (c[3] + bv.y) * g1.y);
                }
            }
        }
    }
}

// ---------------- tensor-core fused causal attention -------------------------
// fp16 qkv in ([B,S,3D] stride 3072), fp16 O out. Softmax in log2 domain.
// K and V fragments loaded via ldmatrix (x4 / x2).
#define AQT 128
#define AKT 64
#define KHSTR 72
#define VSTR 72
#define ATTN_K_BYTES (2 * AKT * KHSTR * 2)
#define ATTN_V_BYTES (2 * HD * VSTR * 2)
#define ATTN_SMEM_BYTES (ATTN_K_BYTES + ATTN_V_BYTES)

__global__ __launch_bounds__(256, 2)
void attn_tc_kernel(const half* __restrict__ QKV,
                    half* __restrict__ O)
{
    extern __shared__ char smraw[];
    half* Ksm = (half*)smraw;
    half* Vsm = (half*)(smraw + ATTN_K_BYTES);

    const int bh = blockIdx.y;
    const int bidx = bh >> 4, hidx = bh & 15;
    const int qt = gridDim.x - 1 - blockIdx.x;   // heaviest tiles first
    const int m0 = qt * AQT;

    const half* Qb = QKV + (size_t)(bidx * SS) * QKVLD + hidx * HD;
    const half* Kb = Qb + DD;
    const half* Vb = Qb + 2 * DD;

    const int tid  = threadIdx.x;
    const int wid  = tid >> 5;
    const int lane = tid & 31;
    const int tg   = lane >> 2;
    const int tq   = lane & 3;

    const int r0 = m0 + wid * 16 + tg;
    const int r1 = r0 + 8;

    const uint32_t kSmLd = (uint32_t)__cvta_generic_to_shared(Ksm) +
                           (uint32_t)(((lane & 7) * KHSTR + (lane >> 3) * 8) * 2);
    const uint32_t vSmLd = (uint32_t)__cvta_generic_to_shared(Vsm) +
                           (uint32_t)(((lane & 7) * VSTR + ((lane >> 3) & 1) * 8) * 2);

    uint32_t qf[4][4];
    {
        const half2 scale = __half2half2(__float2half(0.18033688f));
        const half* q0 = Qb + (size_t)r0 * QKVLD;
        const half* q1 = q0 + 8 * QKVLD;
        #pragma unroll
        for (int kc = 0; kc < 4; kc++) {
            half2 h0 = __hmul2(*(const half2*)(q0 + kc * 16 + 2 * tq), scale);
            half2 h1 = __hmul2(*(const half2*)(q1 + kc * 16 + 2 * tq), scale);
            half2 h2 = __hmul2(*(const half2*)(q0 + kc * 16 + 2 * tq + 8), scale);
            half2 h3 = __hmul2(*(const half2*)(q1 + kc * 16 + 2 * tq + 8), scale);
            qf[kc][0] = *(uint32_t*)&h0;
            qf[kc][1] = *(uint32_t*)&h1;
            qf[kc][2] = *(uint32_t*)&h2;
            qf[kc][3] = *(uint32_t*)&h3;
        }
    }

    float oacc[8][4];
    #pragma unroll
    for (int dt = 0; dt < 8; dt++)
        #pragma unroll
        for (int e = 0; e < 4; e++) oacc[dt][e] = 0.f;
    float mrow0 = -1e30f, mrow1 = -1e30f, lrow0 = 0.f, lrow1 = 0.f;

    auto load_stage = [&](int st, int kt) {
        const int n0 = kt * AKT;
        {
            half* kdst = Ksm + st * AKT * KHSTR;
            int j  = tid >> 2;
            int d0 = (tid & 3) * 16;
            const half* krow = Kb + (size_t)(n0 + j) * QKVLD + d0;
            *(uint4*)(kdst + j * KHSTR + d0)     = *(const uint4*)(krow);
            *(uint4*)(kdst + j * KHSTR + d0 + 8) = *(const uint4*)(krow + 8);
        }
        {
            half* vdst = Vsm + st * HD * VSTR;
            const int d0  = tid & 31;
            const int jp0 = tid >> 5;
            #pragma unroll
            for (int ii = 0; ii < 4; ii++) {
                int jp = jp0 + 8 * ii;
                #pragma unroll
                for (int dd = 0; dd < 2; dd++) {
                    int d = d0 + 32 * dd;
                    half a = Vb[(size_t)(n0 + 2 * jp)     * QKVLD + d];
                    half b = Vb[(size_t)(n0 + 2 * jp + 1) * QKVLD + d];
                    *(half2*)(vdst + d * VSTR + 2 * jp) = __halves2half2(a, b);
                }
            }
        }
    };

    load_stage(0, 0);

    const int ktend = 2 * qt + 1;
    for (int kt = 0; kt <= ktend; kt++) {
        const int s = kt & 1;
        const int n0 = kt * AKT;
        __syncthreads();
        if (kt < ktend) load_stage(s ^ 1, kt + 1);

        const uint32_t kLd = kSmLd + (uint32_t)(s * AKT * KHSTR * 2);
        const uint32_t vLd = vSmLd + (uint32_t)(s * HD * VSTR * 2);

        float sc[8][4];
        #pragma unroll
        for (int nt = 0; nt < 8; nt++) {
            #pragma unroll
            for (int e = 0; e < 4; e++) sc[nt][e] = 0.f;
            #pragma unroll
            for (int kc2 = 0; kc2 < 2; kc2++) {
                uint32_t kf4[4];
                ldsm_x4(kf4, kLd + (uint32_t)((nt * 8 * KHSTR + kc2 * 32) * 2));
                mma_f16(sc[nt], qf[2 * kc2],     kf4);
                mma_f16(sc[nt], qf[2 * kc2 + 1], kf4 + 2);
            }
        }

        if (kt >= 2 * qt) {
            #pragma unroll
            for (int nt = 0; nt < 8; nt++) {
                int jg = n0 + nt * 8 + 2 * tq;
                if (jg     > r0) sc[nt][0] = -1e30f;
                if (jg + 1 > r0) sc[nt][1] = -1e30f;
                if (jg     > r1) sc[nt][2] = -1e30f;
                if (jg + 1 > r1) sc[nt][3] = -1e30f;
            }
        }

        float tm0 = -1e30f, tm1 = -1e30f;
        #pragma unroll
        for (int nt = 0; nt < 8; nt++) {
            tm0 = fmaxf(tm0, fmaxf(sc[nt][0], sc[nt][1]));
            tm1 = fmaxf(tm1, fmaxf(sc[nt][2], sc[nt][3]));
        }
        tm0 = fmaxf(tm0, __shfl_xor_sync(0xffffffffu, tm0, 1));
        tm0 = fmaxf(tm0, __shfl_xor_sync(0xffffffffu, tm0, 2));
        tm1 = fmaxf(tm1, __shfl_xor_sync(0xffffffffu, tm1, 1));
        tm1 = fmaxf(tm1, __shfl_xor_sync(0xffffffffu, tm1, 2));

        float mn0 = fmaxf(mrow0, tm0), mn1 = fmaxf(mrow1, tm1);
        float al0 = ex2(mrow0 - mn0), al1 = ex2(mrow1 - mn1);
        mrow0 = mn0; mrow1 = mn1;

        float sum0 = 0.f, sum1 = 0.f;
        #pragma unroll
        for (int nt = 0; nt < 8; nt++) {
            sc[nt][0] = ex2(sc[nt][0] - mn0); sum0 += sc[nt][0];
            sc[nt][1] = ex2(sc[nt][1] - mn0); sum0 += sc[nt][1];
            sc[nt][2] = ex2(sc[nt][2] - mn1); sum1 += sc[nt][2];
            sc[nt][3] = ex2(sc[nt][3] - mn1); sum1 += sc[nt][3];
        }
        sum0 += __shfl_xor_sync(0xffffffffu, sum0, 1);
        sum0 += __shfl_xor_sync(0xffffffffu, sum0, 2);
        sum1 += __shfl_xor_sync(0xffffffffu, sum1, 1);
        sum1 += __shfl_xor_sync(0xffffffffu, sum1, 2);
        lrow0 = lrow0 * al0 + sum0;
        lrow1 = lrow1 * al1 + sum1;

        #pragma unroll
        for (int dt = 0; dt < 8; dt++) {
            oacc[dt][0] *= al0; oacc[dt][1] *= al0;
            oacc[dt][2] *= al1; oacc[dt][3] *= al1;
        }

        #pragma unroll
        for (int kc = 0; kc < 4; kc++) {
            uint32_t pa[4];
            half2 p0 = __floats2half2_rn(sc[2 * kc][0],     sc[2 * kc][1]);
            half2 p1 = __floats2half2_rn(sc[2 * kc][2],     sc[2 * kc][3]);
            half2 p2 = __floats2half2_rn(sc[2 * kc + 1][0], sc[2 * kc + 1][1]);
            half2 p3 = __floats2half2_rn(sc[2 * kc + 1][2], sc[2 * kc + 1][3]);
            pa[0] = *(uint32_t*)&p0; pa[1] = *(uint32_t*)&p1;
            pa[2] = *(uint32_t*)&p2; pa[3] = *(uint32_t*)&p3;
            #pragma unroll
            for (int dt = 0; dt < 8; dt++) {
                uint32_t vb[2];
                ldsm_x2(vb, vLd + (uint32_t)((dt * 8 * VSTR + kc * 16) * 2));
                mma_f16(oacc[dt], pa, vb);
            }
        }
    }

    const float inv0 = 1.f / lrow0;
    const float inv1 = 1.f / lrow1;
    #pragma unroll
    for (int dt = 0; dt < 8; dt++) {
        int dcol = hidx * HD + dt * 8 + 2 * tq;
        *(half2*)&O[((size_t)(bidx * SS + r0)) * DD + dcol] =
            __floats2half2_rn(oacc[dt][0] * inv0, oacc[dt][1] * inv0);
        *(half2*)&O[((size_t)(bidx * SS + r1)) * DD + dcol] =
            __floats2half2_rn(oacc[dt][2] * inv1, oacc[dt][3] * inv1);
    }
}

// ---------------- launch -----------------------------------------------------
extern "C" void kernel_launch(void* const* d_in, const int* in_sizes, int n_in,
                              void* d_out, int out_size)
{
    const float* x          = (const float*)d_in[0];
    // d_in[1] = mask (unused — causal handled analytically)
    const float* gamma_attn = (const float*)d_in[2];
    const float* w_qkv      = (const float*)d_in[3];
    const float* b_qkv      = (const float*)d_in[4];
    const float* w_out      = (const float*)d_in[5];
    const float* b_out      = (const float*)d_in[6];
    const float* gamma_ffn  = (const float*)d_in[7];
    const float* w1         = (const float*)d_in[8];
    const float* b1         = (const float*)d_in[9];
    const float* w2         = (const float*)d_in[10];
    const float* b2         = (const float*)d_in[11];
    const float* w3         = (const float*)d_in[12];
    const float* b3         = (const float*)d_in[13];
    float* out = (float*)d_out;

    float *xn, *h, *hn, *cost, *sint;
    half *xnh, *qkvh, *oh, *hnh, *ffph, *wqh, *woh, *w1h, *w2h, *w3h;
    cudaGetSymbolAddress((void**)&xn,   g_xn);
    cudaGetSymbolAddress((void**)&xnh,  g_xnh);
    cudaGetSymbolAddress((void**)&qkvh, g_qkvh);
    cudaGetSymbolAddress((void**)&oh,   g_oh);
    cudaGetSymbolAddress((void**)&h,    g_h);
    cudaGetSymbolAddress((void**)&hn,   g_hn);
    cudaGetSymbolAddress((void**)&hnh,  g_hnh);
    cudaGetSymbolAddress((void**)&ffph, g_ffph);
    cudaGetSymbolAddress((void**)&cost, g_cost);
    cudaGetSymbolAddress((void**)&sint, g_sint);
    cudaGetSymbolAddress((void**)&wqh,  g_wqh);
    cudaGetSymbolAddress((void**)&woh,  g_woh);
    cudaGetSymbolAddress((void**)&w1h,  g_w1h);
    cudaGetSymbolAddress((void**)&w2h,  g_w2h);
    cudaGetSymbolAddress((void**)&w3h,  g_w3h);

    cudaFuncSetAttribute(attn_tc_kernel, cudaFuncAttributeMaxDynamicSharedMemorySize,
                         ATTN_SMEM_BYTES);
    cudaFuncSetAttribute(gemm_tc_kernel<1>, cudaFuncAttributeMaxDynamicSharedMemorySize,
                         GEMM_SMEM_BYTES);
    cudaFuncSetAttribute(gemm_tc_kernel<4>, cudaFuncAttributeMaxDynamicSharedMemorySize,
                         GEMM_SMEM_BYTES);
    cudaFuncSetAttribute(gemm_ffn_kernel, cudaFuncAttributeMaxDynamicSharedMemorySize,
                         GEMM_SMEM_BYTES);

    // 0. fused prep: weight fp16 conversions + w3 pad + rope tables
    prep_kernel<<<(PREP_TOTAL + 255) / 256, 256>>>(
        w_qkv, w_out, w1, w2, w3, wqh, woh, w1h, w2h, w3h, cost, sint);

    // 1. xn = rmsnorm(x, gamma_attn)  (fp32 + fp16)
    rmsnorm_kernel<<<MR, 256>>>(x, gamma_attn, xn, xnh);

    // 2. qkvh = half(rope(xn @ w_qkv^T + b_qkv))   [4096 x 3072], K=1024
    gemm_tc_kernel<4><<<dim3(QKVLD / GBN, MR / GBM), 256, GEMM_SMEM_BYTES>>>(
        xnh, wqh, b_qkv, nullptr, nullptr, qkvh, cost, sint,
        MR, QKVLD, DD, QKVLD);

    // 3. fused causal attention (fp16 qkv) -> oh fp16 in [B,S,D]
    attn_tc_kernel<<<dim3(SS / AQT, BB * HH), 256, ATTN_SMEM_BYTES>>>(qkvh, oh);

    // 4. h = xn + o @ w_out^T + b_out              [4096 x 1024], K=1024
    gemm_tc_kernel<1><<<dim3(DD / GBN, MR / GBM), 256, GEMM_SMEM_BYTES>>>(
        oh, woh, b_out, xn, h, nullptr, nullptr, nullptr,
        MR, DD, DD, DD);

    // 5. hn = rmsnorm(h, gamma_ffn)  (fp32 + fp16)
    rmsnorm_kernel<<<MR, 256>>>(h, gamma_ffn, hn, hnh);

    // 6. ffph = half((hn@w1^T+b1) * silu(hn@w2^T+b2))  [4096 x 2730] @ ldc DIP
    gemm_ffn_kernel<<<dim3((DI + 63) / 64, MR / GBM), 256, GEMM_SMEM_BYTES>>>(
        hnh, w1h, w2h, b1, b2, ffph, MR, DI, DD, DIP);

    // 7. out = hn + ffp @ w3^T + b3                [4096 x 1024], K=2752
    gemm_tc_kernel<1><<<dim3(DD / GBN, MR / GBM), 256, GEMM_SMEM_BYTES>>>(
        ffph, w3h, b3, hn, out, nullptr, nullptr, nullptr,
        MR, DD, DIP, DD);
}